// round 12
// baseline (speedup 1.0000x reference)
#include <cuda_runtime.h>
#include <cstdint>
#include <math.h>

#define SEQ 8192
#define DM  2048
#define DK  128

// Scratch (device globals: no allocation allowed)
__device__ float g_Q[SEQ * DK];
__device__ float g_K[SEQ * DK];
__device__ float g_V[SEQ * DK];
__device__ float g_Opart[2 * SEQ * DK];   // unnormalized partial O per KV split
__device__ float g_lpart[2 * SEQ];        // partial row sums per KV split

// ===================== helpers =====================
__device__ __forceinline__ float ex2f(float x) {
    float y; asm("ex2.approx.ftz.f32 %0, %1;" : "=f"(y) : "f"(x)); return y;
}
__device__ __forceinline__ uint32_t to_tf32(float x) {
    uint32_t r; asm("cvt.rna.tf32.f32 %0, %1;" : "=r"(r) : "f"(x)); return r;
}
__device__ __forceinline__ float round_tf32(float x) {
    uint32_t r; asm("cvt.rna.tf32.f32 %0, %1;" : "=r"(r) : "f"(x));
    return __uint_as_float(r);
}
__device__ __forceinline__ uint32_t smem_u32(const void* p) {
    uint32_t a;
    asm("{ .reg .u64 t; cvta.to.shared.u64 t, %1; cvt.u32.u64 %0, t; }" : "=r"(a) : "l"(p));
    return a;
}
// mma.sync m16n8k8 tf32: D = A*B + D
__device__ __forceinline__ void mma8(float& c0, float& c1, float& c2, float& c3,
                                     uint32_t a0, uint32_t a1, uint32_t a2, uint32_t a3,
                                     uint32_t b0, uint32_t b1) {
    asm volatile("mma.sync.aligned.m16n8k8.row.col.f32.tf32.tf32.f32 "
                 "{%0,%1,%2,%3}, {%4,%5,%6,%7}, {%8,%9}, {%0,%1,%2,%3};"
                 : "+f"(c0), "+f"(c1), "+f"(c2), "+f"(c3)
                 : "r"(a0), "r"(a1), "r"(a2), "r"(a3), "r"(b0), "r"(b1));
}
#define CP_ASYNC16(saddr, gaddr) \
    asm volatile("cp.async.cg.shared.global [%0], [%1], 16;" :: "r"(saddr), "l"(gaddr))
#define CP_COMMIT()  asm volatile("cp.async.commit_group;" ::: "memory")
#define CP_WAIT1()   asm volatile("cp.async.wait_group 1;" ::: "memory")
#define CP_WAIT0()   asm volatile("cp.async.wait_group 0;" ::: "memory")

// ============================================================================
// Kernel 1: tf32 mma.sync QKV projection with software-pipelined fragments.
//   out = x @ W^T + b.  grid (64,1,3), 256 thr = 8 warps 4(M)x2(N).
//   A-frags for the whole BK=32 tile preloaded; B-frags 2-deep ping-pong.
//   K/V outputs stored pre-rounded to tf32 (attention feeds them raw to mma).
// ============================================================================
#define PK_STRIDE 36
#define PBUF_F (128 * PK_STRIDE)
#define PROJ_SMEM_B (4 * PBUF_F * 4)        // 73728 bytes

__global__ __launch_bounds__(256)
void proj_tc_kernel(const float* __restrict__ x,
                    const float* __restrict__ Wq, const float* __restrict__ bq,
                    const float* __restrict__ Wk, const float* __restrict__ bk,
                    const float* __restrict__ Wv, const float* __restrict__ bv)
{
    const float* W; const float* bias; float* out;
    if (blockIdx.z == 0)      { W = Wq; bias = bq; out = g_Q; }
    else if (blockIdx.z == 1) { W = Wk; bias = bk; out = g_K; }
    else                      { W = Wv; bias = bv; out = g_V; }
    const bool roundOut = (blockIdx.z != 0);

    extern __shared__ float psm[];
    float* xs = psm;                 // [2][128][36] tf32
    float* ws = psm + 2 * PBUF_F;    // [2][128][36] tf32

    const int tid  = threadIdx.x;
    const int wid  = tid >> 5;
    const int lane = tid & 31;
    const int gid  = lane >> 2;
    const int qid  = lane & 3;
    const int wr   = wid & 3;
    const int wc   = wid >> 2;
    const int rowBase = blockIdx.x * 128;

    float o[2][8][4];
    #pragma unroll
    for (int mi = 0; mi < 2; mi++)
        #pragma unroll
        for (int j = 0; j < 8; j++)
            #pragma unroll
            for (int i = 0; i < 4; i++) o[mi][j][i] = 0.f;

    float4 xr[4], wrg[4];

    #pragma unroll
    for (int l = 0; l < 4; l++) {
        int idx = tid + l * 256;
        int r = idx >> 3, q = (idx & 7) * 4;
        xr[l]  = *(const float4*)&x[(size_t)(rowBase + r) * DM + q];
        wrg[l] = *(const float4*)&W[(size_t)r * DM + q];
    }
    #pragma unroll
    for (int l = 0; l < 4; l++) {
        int idx = tid + l * 256;
        int r = idx >> 3, q = (idx & 7) * 4;
        uint4 u;
        u.x = to_tf32(xr[l].x);  u.y = to_tf32(xr[l].y);
        u.z = to_tf32(xr[l].z);  u.w = to_tf32(xr[l].w);
        *(uint4*)&xs[r * PK_STRIDE + q] = u;
        uint4 v;
        v.x = to_tf32(wrg[l].x); v.y = to_tf32(wrg[l].y);
        v.z = to_tf32(wrg[l].z); v.w = to_tf32(wrg[l].w);
        *(uint4*)&ws[r * PK_STRIDE + q] = v;
    }
    __syncthreads();

    const int arow0 = wr * 32 + gid;          // mi=0 row
    const int arow1 = wr * 32 + 16 + gid;     // mi=1 row

    for (int t = 0; t < 64; t++) {
        if (t < 63) {
            const int k0 = (t + 1) * 32;
            #pragma unroll
            for (int l = 0; l < 4; l++) {
                int idx = tid + l * 256;
                int r = idx >> 3, q = (idx & 7) * 4;
                xr[l]  = *(const float4*)&x[(size_t)(rowBase + r) * DM + k0 + q];
                wrg[l] = *(const float4*)&W[(size_t)r * DM + k0 + q];
            }
        }

        const float* xb = xs + (t & 1) * PBUF_F;
        const float* wb = ws + (t & 1) * PBUF_F;

        // ---- preload ALL A fragments for this BK=32 tile ----
        uint32_t a[4][2][4];
        #pragma unroll
        for (int ks = 0; ks < 4; ks++) {
            const int k = ks * 8;
            a[ks][0][0] = __float_as_uint(xb[arow0       * PK_STRIDE + k + qid]);
            a[ks][0][1] = __float_as_uint(xb[(arow0 + 8) * PK_STRIDE + k + qid]);
            a[ks][0][2] = __float_as_uint(xb[arow0       * PK_STRIDE + k + qid + 4]);
            a[ks][0][3] = __float_as_uint(xb[(arow0 + 8) * PK_STRIDE + k + qid + 4]);
            a[ks][1][0] = __float_as_uint(xb[arow1       * PK_STRIDE + k + qid]);
            a[ks][1][1] = __float_as_uint(xb[(arow1 + 8) * PK_STRIDE + k + qid]);
            a[ks][1][2] = __float_as_uint(xb[arow1       * PK_STRIDE + k + qid + 4]);
            a[ks][1][3] = __float_as_uint(xb[(arow1 + 8) * PK_STRIDE + k + qid + 4]);
        }

        // ---- B fragments: 2-deep register ping-pong across ks ----
        uint32_t bb[2][2][8];
        #pragma unroll
        for (int j = 0; j < 8; j++) {
            int n = wc * 64 + 8 * j + gid;
            bb[0][0][j] = __float_as_uint(wb[n * PK_STRIDE + qid]);
            bb[0][1][j] = __float_as_uint(wb[n * PK_STRIDE + qid + 4]);
        }
        #pragma unroll
        for (int ks = 0; ks < 4; ks++) {
            const int cur = ks & 1;
            if (ks < 3) {
                const int k = (ks + 1) * 8;
                #pragma unroll
                for (int j = 0; j < 8; j++) {
                    int n = wc * 64 + 8 * j + gid;
                    bb[cur ^ 1][0][j] = __float_as_uint(wb[n * PK_STRIDE + k + qid]);
                    bb[cur ^ 1][1][j] = __float_as_uint(wb[n * PK_STRIDE + k + qid + 4]);
                }
            }
            #pragma unroll
            for (int j = 0; j < 8; j++) {
                mma8(o[0][j][0], o[0][j][1], o[0][j][2], o[0][j][3],
                     a[ks][0][0], a[ks][0][1], a[ks][0][2], a[ks][0][3],
                     bb[cur][0][j], bb[cur][1][j]);
                mma8(o[1][j][0], o[1][j][1], o[1][j][2], o[1][j][3],
                     a[ks][1][0], a[ks][1][1], a[ks][1][2], a[ks][1][3],
                     bb[cur][0][j], bb[cur][1][j]);
            }
        }

        if (t < 63) {
            float* xn = xs + ((t + 1) & 1) * PBUF_F;
            float* wn = ws + ((t + 1) & 1) * PBUF_F;
            #pragma unroll
            for (int l = 0; l < 4; l++) {
                int idx = tid + l * 256;
                int r = idx >> 3, q = (idx & 7) * 4;
                uint4 u;
                u.x = to_tf32(xr[l].x);  u.y = to_tf32(xr[l].y);
                u.z = to_tf32(xr[l].z);  u.w = to_tf32(xr[l].w);
                *(uint4*)&xn[r * PK_STRIDE + q] = u;
                uint4 v;
                v.x = to_tf32(wrg[l].x); v.y = to_tf32(wrg[l].y);
                v.z = to_tf32(wrg[l].z); v.w = to_tf32(wrg[l].w);
                *(uint4*)&wn[r * PK_STRIDE + q] = v;
            }
        }
        __syncthreads();
    }

    #pragma unroll
    for (int mi = 0; mi < 2; mi++) {
        int row = rowBase + wr * 32 + mi * 16 + gid;
        #pragma unroll
        for (int j = 0; j < 8; j++) {
            int col = wc * 64 + 8 * j + 2 * qid;
            float2 bb2 = *(const float2*)&bias[col];
            float v00 = o[mi][j][0] + bb2.x, v01 = o[mi][j][1] + bb2.y;
            float v10 = o[mi][j][2] + bb2.x, v11 = o[mi][j][3] + bb2.y;
            if (roundOut) {
                v00 = round_tf32(v00); v01 = round_tf32(v01);
                v10 = round_tf32(v10); v11 = round_tf32(v11);
            }
            *(float2*)&out[(size_t)row * DK + col]       = make_float2(v00, v01);
            *(float2*)&out[(size_t)(row + 8) * DK + col] = make_float2(v10, v11);
        }
    }
}

// ============================================================================
// Kernel 2: tf32 mma.sync flash attention (UNCHANGED from R11 pass).
// ============================================================================
#define KV_BUF_F  (64 * 132 + 64 * 136)       // 17152 floats per buffer
#define V_OFF_F   (64 * 132)
#define P_F       (2 * KV_BUF_F)              // 34304
#define ATTN_SMEM_B ((P_F + 128 * 68) * 4)    // 172032 bytes

__global__ __launch_bounds__(256)
void attn_kernel()
{
    extern __shared__ float sm[];
    const uint32_t smb = smem_u32(sm);
    const int tid  = threadIdx.x;
    const int wid  = tid >> 5;
    const int lane = tid & 31;
    const int gid  = lane >> 2;
    const int qid  = lane & 3;
    const int qbase = blockIdx.x * 128;
    const int split = blockIdx.y;
    const int r0 = (wid << 4) + gid;
    const int kvbase = split * 4096;

    const float qscale = 1.4426950408889634f * 0.08838834764831845f;
    uint32_t qf[16][4];
    {
        const float* q0 = &g_Q[(size_t)(qbase + r0) * DK];
        const float* q1 = &g_Q[(size_t)(qbase + r0 + 8) * DK];
        #pragma unroll
        for (int ks = 0; ks < 16; ks++) {
            const int k = ks * 8;
            qf[ks][0] = to_tf32(q0[k + qid]     * qscale);
            qf[ks][1] = to_tf32(q1[k + qid]     * qscale);
            qf[ks][2] = to_tf32(q0[k + qid + 4] * qscale);
            qf[ks][3] = to_tf32(q1[k + qid + 4] * qscale);
        }
    }

    float o[16][4];
    #pragma unroll
    for (int j = 0; j < 16; j++)
        #pragma unroll
        for (int i = 0; i < 4; i++) o[j][i] = 0.f;
    float lsum0 = 0.f, lsum1 = 0.f;

    auto issue_tile = [&](int t, int b) {
        const int kv0 = kvbase + t * 64;
        const uint32_t bb = smb + (uint32_t)(b * KV_BUF_F) * 4u;
        #pragma unroll
        for (int l = 0; l < 8; l++) {
            int idx = tid + l * 256;
            int r = idx >> 5, q = (idx & 31) * 4;
            CP_ASYNC16(bb + (uint32_t)(r * 132 + q) * 4u,
                       &g_K[(size_t)(kv0 + r) * DK + q]);
            CP_ASYNC16(bb + (uint32_t)(V_OFF_F + r * 136 + q) * 4u,
                       &g_V[(size_t)(kv0 + r) * DK + q]);
        }
        CP_COMMIT();
    };

    issue_tile(0, 0);

    for (int t = 0; t < 64; t++) {
        if (t < 63) { issue_tile(t + 1, (t + 1) & 1); CP_WAIT1(); }
        else        { CP_WAIT0(); }
        __syncthreads();

        const float* kb = sm + (t & 1) * KV_BUF_F;
        const float* vb = kb + V_OFF_F;

        float s[8][4];
        #pragma unroll
        for (int j = 0; j < 8; j++)
            #pragma unroll
            for (int i = 0; i < 4; i++) s[j][i] = 0.f;

        uint32_t bbuf[2][2][8];
        #pragma unroll
        for (int j = 0; j < 8; j++) {
            bbuf[0][0][j] = __float_as_uint(kb[(8 * j + gid) * 132 + qid]);
            bbuf[0][1][j] = __float_as_uint(kb[(8 * j + gid) * 132 + qid + 4]);
        }
        #pragma unroll
        for (int ks = 0; ks < 16; ks++) {
            const int cur = ks & 1;
            if (ks < 15) {
                const int k = (ks + 1) * 8;
                #pragma unroll
                for (int j = 0; j < 8; j++) {
                    bbuf[cur ^ 1][0][j] = __float_as_uint(kb[(8 * j + gid) * 132 + k + qid]);
                    bbuf[cur ^ 1][1][j] = __float_as_uint(kb[(8 * j + gid) * 132 + k + qid + 4]);
                }
            }
            #pragma unroll
            for (int j = 0; j < 8; j++)
                mma8(s[j][0], s[j][1], s[j][2], s[j][3],
                     qf[ks][0], qf[ks][1], qf[ks][2], qf[ks][3],
                     bbuf[cur][0][j], bbuf[cur][1][j]);
        }

        float ps0 = 0.f, ps1 = 0.f;
        #pragma unroll
        for (int j = 0; j < 8; j++) {
            s[j][0] = ex2f(s[j][0]); s[j][1] = ex2f(s[j][1]);
            s[j][2] = ex2f(s[j][2]); s[j][3] = ex2f(s[j][3]);
            ps0 += s[j][0] + s[j][1];
            ps1 += s[j][2] + s[j][3];
        }
        ps0 += __shfl_xor_sync(0xffffffffu, ps0, 1);
        ps0 += __shfl_xor_sync(0xffffffffu, ps0, 2);
        ps1 += __shfl_xor_sync(0xffffffffu, ps1, 1);
        ps1 += __shfl_xor_sync(0xffffffffu, ps1, 2);
        lsum0 += ps0; lsum1 += ps1;

        #pragma unroll
        for (int j = 0; j < 8; j++) {
            uint2 p0; p0.x = to_tf32(s[j][0]); p0.y = to_tf32(s[j][1]);
            *(uint2*)&sm[P_F + r0 * 68 + 8 * j + 2 * qid] = p0;
            uint2 p1; p1.x = to_tf32(s[j][2]); p1.y = to_tf32(s[j][3]);
            *(uint2*)&sm[P_F + (r0 + 8) * 68 + 8 * j + 2 * qid] = p1;
        }
        __syncwarp();

        #pragma unroll
        for (int ks = 0; ks < 8; ks++) {
            const int k = ks * 8;
            uint32_t a0 = __float_as_uint(sm[P_F + r0       * 68 + k + qid]);
            uint32_t a1 = __float_as_uint(sm[P_F + (r0 + 8) * 68 + k + qid]);
            uint32_t a2 = __float_as_uint(sm[P_F + r0       * 68 + k + qid + 4]);
            uint32_t a3 = __float_as_uint(sm[P_F + (r0 + 8) * 68 + k + qid + 4]);
            uint32_t c0[8], c1[8], d0[8], d1[8];
            #pragma unroll
            for (int j = 0; j < 8; j++) {
                c0[j] = __float_as_uint(vb[(k + qid)     * 136 + 8 * j + gid]);
                c1[j] = __float_as_uint(vb[(k + qid + 4) * 136 + 8 * j + gid]);
            }
            #pragma unroll
            for (int j = 0; j < 8; j++) {
                d0[j] = __float_as_uint(vb[(k + qid)     * 136 + 64 + 8 * j + gid]);
                d1[j] = __float_as_uint(vb[(k + qid + 4) * 136 + 64 + 8 * j + gid]);
            }
            #pragma unroll
            for (int j = 0; j < 8; j++)
                mma8(o[j][0], o[j][1], o[j][2], o[j][3], a0, a1, a2, a3, c0[j], c1[j]);
            #pragma unroll
            for (int j = 0; j < 8; j++)
                mma8(o[8 + j][0], o[8 + j][1], o[8 + j][2], o[8 + j][3],
                     a0, a1, a2, a3, d0[j], d1[j]);
        }
        __syncthreads();
    }

    float* Op = g_Opart + (size_t)split * SEQ * DK;
    #pragma unroll
    for (int j = 0; j < 16; j++) {
        int col = 8 * j + 2 * qid;
        *(float2*)&Op[(size_t)(qbase + r0) * DK + col]     = make_float2(o[j][0], o[j][1]);
        *(float2*)&Op[(size_t)(qbase + r0 + 8) * DK + col] = make_float2(o[j][2], o[j][3]);
    }
    if (qid == 0) {
        g_lpart[split * SEQ + qbase + r0]     = lsum0;
        g_lpart[split * SEQ + qbase + r0 + 8] = lsum1;
    }
}

// ============================================================================
// Kernel 3: combine splits.  out = (O0 + O1) / (l0 + l1)
// ============================================================================
__global__ __launch_bounds__(256)
void combine_kernel(float* __restrict__ out)
{
    int idx = blockIdx.x * 256 + threadIdx.x;
    int r = idx >> 5, c4 = (idx & 31) * 4;
    float inv = 1.f / (g_lpart[r] + g_lpart[SEQ + r]);
    float4 a = *(const float4*)&g_Opart[(size_t)r * DK + c4];
    float4 b = *(const float4*)&g_Opart[(size_t)(SEQ + r) * DK + c4];
    float4 o;
    o.x = (a.x + b.x) * inv; o.y = (a.y + b.y) * inv;
    o.z = (a.z + b.z) * inv; o.w = (a.w + b.w) * inv;
    *(float4*)&out[(size_t)r * DK + c4] = o;
}

// ---------------------------------------------------------------------------
extern "C" void kernel_launch(void* const* d_in, const int* in_sizes, int n_in,
                              void* d_out, int out_size)
{
    (void)in_sizes; (void)n_in; (void)out_size;
    const float* x  = (const float*)d_in[0];
    const float* Wq = (const float*)d_in[1];
    const float* bq = (const float*)d_in[2];
    const float* Wk = (const float*)d_in[3];
    const float* bk = (const float*)d_in[4];
    const float* Wv = (const float*)d_in[5];
    const float* bv = (const float*)d_in[6];
    float* out = (float*)d_out;

    cudaFuncSetAttribute(proj_tc_kernel,
                         cudaFuncAttributeMaxDynamicSharedMemorySize, PROJ_SMEM_B);
    cudaFuncSetAttribute(attn_kernel,
                         cudaFuncAttributeMaxDynamicSharedMemorySize, ATTN_SMEM_B);

    dim3 gProj(SEQ / 128, 1, 3);
    proj_tc_kernel<<<gProj, 256, PROJ_SMEM_B>>>(x, Wq, bq, Wk, bk, Wv, bv);

    dim3 gAttn(SEQ / 128, 2);
    attn_kernel<<<gAttn, 256, ATTN_SMEM_B>>>();

    combine_kernel<<<SEQ * DK / 4 / 256, 256>>>(out);
}

// round 13
// speedup vs baseline: 1.0096x; 1.0096x over previous
#include <cuda_runtime.h>
#include <cstdint>
#include <math.h>

#define SEQ 8192
#define DM  2048
#define DK  128

// Scratch (device globals: no allocation allowed)
__device__ float g_Q[SEQ * DK];
__device__ float g_K[SEQ * DK];
__device__ float g_V[SEQ * DK];
__device__ float g_Opart[2 * SEQ * DK];   // unnormalized partial O per KV split
__device__ float g_lpart[2 * SEQ];        // partial row sums per KV split

// ===================== helpers =====================
__device__ __forceinline__ float ex2f(float x) {
    float y; asm("ex2.approx.ftz.f32 %0, %1;" : "=f"(y) : "f"(x)); return y;
}
__device__ __forceinline__ uint32_t to_tf32(float x) {
    uint32_t r; asm("cvt.rna.tf32.f32 %0, %1;" : "=r"(r) : "f"(x)); return r;
}
__device__ __forceinline__ float round_tf32(float x) {
    uint32_t r; asm("cvt.rna.tf32.f32 %0, %1;" : "=r"(r) : "f"(x));
    return __uint_as_float(r);
}
__device__ __forceinline__ uint32_t smem_u32(const void* p) {
    uint32_t a;
    asm("{ .reg .u64 t; cvta.to.shared.u64 t, %1; cvt.u32.u64 %0, t; }" : "=r"(a) : "l"(p));
    return a;
}
// mma.sync m16n8k8 tf32: D = A*B + D
__device__ __forceinline__ void mma8(float& c0, float& c1, float& c2, float& c3,
                                     uint32_t a0, uint32_t a1, uint32_t a2, uint32_t a3,
                                     uint32_t b0, uint32_t b1) {
    asm volatile("mma.sync.aligned.m16n8k8.row.col.f32.tf32.tf32.f32 "
                 "{%0,%1,%2,%3}, {%4,%5,%6,%7}, {%8,%9}, {%0,%1,%2,%3};"
                 : "+f"(c0), "+f"(c1), "+f"(c2), "+f"(c3)
                 : "r"(a0), "r"(a1), "r"(a2), "r"(a3), "r"(b0), "r"(b1));
}
#define CP_ASYNC16(saddr, gaddr) \
    asm volatile("cp.async.cg.shared.global [%0], [%1], 16;" :: "r"(saddr), "l"(gaddr))
#define CP_COMMIT()  asm volatile("cp.async.commit_group;" ::: "memory")
#define CP_WAIT1()   asm volatile("cp.async.wait_group 1;" ::: "memory")
#define CP_WAIT0()   asm volatile("cp.async.wait_group 0;" ::: "memory")

// ============================================================================
// Kernel 1: tf32 mma.sync QKV projection.  out = x @ W^T + b
//   grid (64,1,3), 256 thr = 8 warps 4(M)x2(N), BK=32, double-buffered smem.
//   __launch_bounds__(256, 2): 2 CTAs/SM -> all 192 CTAs co-resident,
//   4 warps/SMSP for latency hiding (this round's change).
//   K/V outputs stored pre-rounded to tf32.
// ============================================================================
#define PK_STRIDE 36
#define PBUF_F (128 * PK_STRIDE)
#define PROJ_SMEM_B (4 * PBUF_F * 4)        // 73728 bytes

__global__ __launch_bounds__(256, 2)
void proj_tc_kernel(const float* __restrict__ x,
                    const float* __restrict__ Wq, const float* __restrict__ bq,
                    const float* __restrict__ Wk, const float* __restrict__ bk,
                    const float* __restrict__ Wv, const float* __restrict__ bv)
{
    const float* W; const float* bias; float* out;
    if (blockIdx.z == 0)      { W = Wq; bias = bq; out = g_Q; }
    else if (blockIdx.z == 1) { W = Wk; bias = bk; out = g_K; }
    else                      { W = Wv; bias = bv; out = g_V; }
    const bool roundOut = (blockIdx.z != 0);

    extern __shared__ float psm[];
    float* xs = psm;                 // [2][128][36] tf32
    float* ws = psm + 2 * PBUF_F;    // [2][128][36] tf32

    const int tid  = threadIdx.x;
    const int wid  = tid >> 5;
    const int lane = tid & 31;
    const int gid  = lane >> 2;
    const int qid  = lane & 3;
    const int wr   = wid & 3;
    const int wc   = wid >> 2;
    const int rowBase = blockIdx.x * 128;

    float o[2][8][4];
    #pragma unroll
    for (int mi = 0; mi < 2; mi++)
        #pragma unroll
        for (int j = 0; j < 8; j++)
            #pragma unroll
            for (int i = 0; i < 4; i++) o[mi][j][i] = 0.f;

    float4 xr[4], wrg[4];

    #pragma unroll
    for (int l = 0; l < 4; l++) {
        int idx = tid + l * 256;
        int r = idx >> 3, q = (idx & 7) * 4;
        xr[l]  = *(const float4*)&x[(size_t)(rowBase + r) * DM + q];
        wrg[l] = *(const float4*)&W[(size_t)r * DM + q];
    }
    #pragma unroll
    for (int l = 0; l < 4; l++) {
        int idx = tid + l * 256;
        int r = idx >> 3, q = (idx & 7) * 4;
        uint4 u;
        u.x = to_tf32(xr[l].x);  u.y = to_tf32(xr[l].y);
        u.z = to_tf32(xr[l].z);  u.w = to_tf32(xr[l].w);
        *(uint4*)&xs[r * PK_STRIDE + q] = u;
        uint4 v;
        v.x = to_tf32(wrg[l].x); v.y = to_tf32(wrg[l].y);
        v.z = to_tf32(wrg[l].z); v.w = to_tf32(wrg[l].w);
        *(uint4*)&ws[r * PK_STRIDE + q] = v;
    }
    __syncthreads();

    const int arow0 = wr * 32 + gid;
    const int arow1 = wr * 32 + 16 + gid;

    for (int t = 0; t < 64; t++) {
        if (t < 63) {
            const int k0 = (t + 1) * 32;
            #pragma unroll
            for (int l = 0; l < 4; l++) {
                int idx = tid + l * 256;
                int r = idx >> 3, q = (idx & 7) * 4;
                xr[l]  = *(const float4*)&x[(size_t)(rowBase + r) * DM + k0 + q];
                wrg[l] = *(const float4*)&W[(size_t)r * DM + k0 + q];
            }
        }

        const float* xb = xs + (t & 1) * PBUF_F;
        const float* wb = ws + (t & 1) * PBUF_F;

        uint32_t a[4][2][4];
        #pragma unroll
        for (int ks = 0; ks < 4; ks++) {
            const int k = ks * 8;
            a[ks][0][0] = __float_as_uint(xb[arow0       * PK_STRIDE + k + qid]);
            a[ks][0][1] = __float_as_uint(xb[(arow0 + 8) * PK_STRIDE + k + qid]);
            a[ks][0][2] = __float_as_uint(xb[arow0       * PK_STRIDE + k + qid + 4]);
            a[ks][0][3] = __float_as_uint(xb[(arow0 + 8) * PK_STRIDE + k + qid + 4]);
            a[ks][1][0] = __float_as_uint(xb[arow1       * PK_STRIDE + k + qid]);
            a[ks][1][1] = __float_as_uint(xb[(arow1 + 8) * PK_STRIDE + k + qid]);
            a[ks][1][2] = __float_as_uint(xb[arow1       * PK_STRIDE + k + qid + 4]);
            a[ks][1][3] = __float_as_uint(xb[(arow1 + 8) * PK_STRIDE + k + qid + 4]);
        }

        uint32_t bb[2][2][8];
        #pragma unroll
        for (int j = 0; j < 8; j++) {
            int n = wc * 64 + 8 * j + gid;
            bb[0][0][j] = __float_as_uint(wb[n * PK_STRIDE + qid]);
            bb[0][1][j] = __float_as_uint(wb[n * PK_STRIDE + qid + 4]);
        }
        #pragma unroll
        for (int ks = 0; ks < 4; ks++) {
            const int cur = ks & 1;
            if (ks < 3) {
                const int k = (ks + 1) * 8;
                #pragma unroll
                for (int j = 0; j < 8; j++) {
                    int n = wc * 64 + 8 * j + gid;
                    bb[cur ^ 1][0][j] = __float_as_uint(wb[n * PK_STRIDE + k + qid]);
                    bb[cur ^ 1][1][j] = __float_as_uint(wb[n * PK_STRIDE + k + qid + 4]);
                }
            }
            #pragma unroll
            for (int j = 0; j < 8; j++) {
                mma8(o[0][j][0], o[0][j][1], o[0][j][2], o[0][j][3],
                     a[ks][0][0], a[ks][0][1], a[ks][0][2], a[ks][0][3],
                     bb[cur][0][j], bb[cur][1][j]);
                mma8(o[1][j][0], o[1][j][1], o[1][j][2], o[1][j][3],
                     a[ks][1][0], a[ks][1][1], a[ks][1][2], a[ks][1][3],
                     bb[cur][0][j], bb[cur][1][j]);
            }
        }

        if (t < 63) {
            float* xn = xs + ((t + 1) & 1) * PBUF_F;
            float* wn = ws + ((t + 1) & 1) * PBUF_F;
            #pragma unroll
            for (int l = 0; l < 4; l++) {
                int idx = tid + l * 256;
                int r = idx >> 3, q = (idx & 7) * 4;
                uint4 u;
                u.x = to_tf32(xr[l].x);  u.y = to_tf32(xr[l].y);
                u.z = to_tf32(xr[l].z);  u.w = to_tf32(xr[l].w);
                *(uint4*)&xn[r * PK_STRIDE + q] = u;
                uint4 v;
                v.x = to_tf32(wrg[l].x); v.y = to_tf32(wrg[l].y);
                v.z = to_tf32(wrg[l].z); v.w = to_tf32(wrg[l].w);
                *(uint4*)&wn[r * PK_STRIDE + q] = v;
            }
        }
        __syncthreads();
    }

    #pragma unroll
    for (int mi = 0; mi < 2; mi++) {
        int row = rowBase + wr * 32 + mi * 16 + gid;
        #pragma unroll
        for (int j = 0; j < 8; j++) {
            int col = wc * 64 + 8 * j + 2 * qid;
            float2 bb2 = *(const float2*)&bias[col];
            float v00 = o[mi][j][0] + bb2.x, v01 = o[mi][j][1] + bb2.y;
            float v10 = o[mi][j][2] + bb2.x, v11 = o[mi][j][3] + bb2.y;
            if (roundOut) {
                v00 = round_tf32(v00); v01 = round_tf32(v01);
                v10 = round_tf32(v10); v11 = round_tf32(v11);
            }
            *(float2*)&out[(size_t)row * DK + col]       = make_float2(v00, v01);
            *(float2*)&out[(size_t)(row + 8) * DK + col] = make_float2(v10, v11);
        }
    }
}

// ============================================================================
// Kernel 2: tf32 mma.sync flash attention (UNCHANGED from R11/R12 pass).
// ============================================================================
#define KV_BUF_F  (64 * 132 + 64 * 136)       // 17152 floats per buffer
#define V_OFF_F   (64 * 132)
#define P_F       (2 * KV_BUF_F)              // 34304
#define ATTN_SMEM_B ((P_F + 128 * 68) * 4)    // 172032 bytes

__global__ __launch_bounds__(256)
void attn_kernel()
{
    extern __shared__ float sm[];
    const uint32_t smb = smem_u32(sm);
    const int tid  = threadIdx.x;
    const int wid  = tid >> 5;
    const int lane = tid & 31;
    const int gid  = lane >> 2;
    const int qid  = lane & 3;
    const int qbase = blockIdx.x * 128;
    const int split = blockIdx.y;
    const int r0 = (wid << 4) + gid;
    const int kvbase = split * 4096;

    const float qscale = 1.4426950408889634f * 0.08838834764831845f;
    uint32_t qf[16][4];
    {
        const float* q0 = &g_Q[(size_t)(qbase + r0) * DK];
        const float* q1 = &g_Q[(size_t)(qbase + r0 + 8) * DK];
        #pragma unroll
        for (int ks = 0; ks < 16; ks++) {
            const int k = ks * 8;
            qf[ks][0] = to_tf32(q0[k + qid]     * qscale);
            qf[ks][1] = to_tf32(q1[k + qid]     * qscale);
            qf[ks][2] = to_tf32(q0[k + qid + 4] * qscale);
            qf[ks][3] = to_tf32(q1[k + qid + 4] * qscale);
        }
    }

    float o[16][4];
    #pragma unroll
    for (int j = 0; j < 16; j++)
        #pragma unroll
        for (int i = 0; i < 4; i++) o[j][i] = 0.f;
    float lsum0 = 0.f, lsum1 = 0.f;

    auto issue_tile = [&](int t, int b) {
        const int kv0 = kvbase + t * 64;
        const uint32_t bb = smb + (uint32_t)(b * KV_BUF_F) * 4u;
        #pragma unroll
        for (int l = 0; l < 8; l++) {
            int idx = tid + l * 256;
            int r = idx >> 5, q = (idx & 31) * 4;
            CP_ASYNC16(bb + (uint32_t)(r * 132 + q) * 4u,
                       &g_K[(size_t)(kv0 + r) * DK + q]);
            CP_ASYNC16(bb + (uint32_t)(V_OFF_F + r * 136 + q) * 4u,
                       &g_V[(size_t)(kv0 + r) * DK + q]);
        }
        CP_COMMIT();
    };

    issue_tile(0, 0);

    for (int t = 0; t < 64; t++) {
        if (t < 63) { issue_tile(t + 1, (t + 1) & 1); CP_WAIT1(); }
        else        { CP_WAIT0(); }
        __syncthreads();

        const float* kb = sm + (t & 1) * KV_BUF_F;
        const float* vb = kb + V_OFF_F;

        float s[8][4];
        #pragma unroll
        for (int j = 0; j < 8; j++)
            #pragma unroll
            for (int i = 0; i < 4; i++) s[j][i] = 0.f;

        uint32_t bbuf[2][2][8];
        #pragma unroll
        for (int j = 0; j < 8; j++) {
            bbuf[0][0][j] = __float_as_uint(kb[(8 * j + gid) * 132 + qid]);
            bbuf[0][1][j] = __float_as_uint(kb[(8 * j + gid) * 132 + qid + 4]);
        }
        #pragma unroll
        for (int ks = 0; ks < 16; ks++) {
            const int cur = ks & 1;
            if (ks < 15) {
                const int k = (ks + 1) * 8;
                #pragma unroll
                for (int j = 0; j < 8; j++) {
                    bbuf[cur ^ 1][0][j] = __float_as_uint(kb[(8 * j + gid) * 132 + k + qid]);
                    bbuf[cur ^ 1][1][j] = __float_as_uint(kb[(8 * j + gid) * 132 + k + qid + 4]);
                }
            }
            #pragma unroll
            for (int j = 0; j < 8; j++)
                mma8(s[j][0], s[j][1], s[j][2], s[j][3],
                     qf[ks][0], qf[ks][1], qf[ks][2], qf[ks][3],
                     bbuf[cur][0][j], bbuf[cur][1][j]);
        }

        float ps0 = 0.f, ps1 = 0.f;
        #pragma unroll
        for (int j = 0; j < 8; j++) {
            s[j][0] = ex2f(s[j][0]); s[j][1] = ex2f(s[j][1]);
            s[j][2] = ex2f(s[j][2]); s[j][3] = ex2f(s[j][3]);
            ps0 += s[j][0] + s[j][1];
            ps1 += s[j][2] + s[j][3];
        }
        ps0 += __shfl_xor_sync(0xffffffffu, ps0, 1);
        ps0 += __shfl_xor_sync(0xffffffffu, ps0, 2);
        ps1 += __shfl_xor_sync(0xffffffffu, ps1, 1);
        ps1 += __shfl_xor_sync(0xffffffffu, ps1, 2);
        lsum0 += ps0; lsum1 += ps1;

        #pragma unroll
        for (int j = 0; j < 8; j++) {
            uint2 p0; p0.x = to_tf32(s[j][0]); p0.y = to_tf32(s[j][1]);
            *(uint2*)&sm[P_F + r0 * 68 + 8 * j + 2 * qid] = p0;
            uint2 p1; p1.x = to_tf32(s[j][2]); p1.y = to_tf32(s[j][3]);
            *(uint2*)&sm[P_F + (r0 + 8) * 68 + 8 * j + 2 * qid] = p1;
        }
        __syncwarp();

        #pragma unroll
        for (int ks = 0; ks < 8; ks++) {
            const int k = ks * 8;
            uint32_t a0 = __float_as_uint(sm[P_F + r0       * 68 + k + qid]);
            uint32_t a1 = __float_as_uint(sm[P_F + (r0 + 8) * 68 + k + qid]);
            uint32_t a2 = __float_as_uint(sm[P_F + r0       * 68 + k + qid + 4]);
            uint32_t a3 = __float_as_uint(sm[P_F + (r0 + 8) * 68 + k + qid + 4]);
            uint32_t c0[8], c1[8], d0[8], d1[8];
            #pragma unroll
            for (int j = 0; j < 8; j++) {
                c0[j] = __float_as_uint(vb[(k + qid)     * 136 + 8 * j + gid]);
                c1[j] = __float_as_uint(vb[(k + qid + 4) * 136 + 8 * j + gid]);
            }
            #pragma unroll
            for (int j = 0; j < 8; j++) {
                d0[j] = __float_as_uint(vb[(k + qid)     * 136 + 64 + 8 * j + gid]);
                d1[j] = __float_as_uint(vb[(k + qid + 4) * 136 + 64 + 8 * j + gid]);
            }
            #pragma unroll
            for (int j = 0; j < 8; j++)
                mma8(o[j][0], o[j][1], o[j][2], o[j][3], a0, a1, a2, a3, c0[j], c1[j]);
            #pragma unroll
            for (int j = 0; j < 8; j++)
                mma8(o[8 + j][0], o[8 + j][1], o[8 + j][2], o[8 + j][3],
                     a0, a1, a2, a3, d0[j], d1[j]);
        }
        __syncthreads();
    }

    float* Op = g_Opart + (size_t)split * SEQ * DK;
    #pragma unroll
    for (int j = 0; j < 16; j++) {
        int col = 8 * j + 2 * qid;
        *(float2*)&Op[(size_t)(qbase + r0) * DK + col]     = make_float2(o[j][0], o[j][1]);
        *(float2*)&Op[(size_t)(qbase + r0 + 8) * DK + col] = make_float2(o[j][2], o[j][3]);
    }
    if (qid == 0) {
        g_lpart[split * SEQ + qbase + r0]     = lsum0;
        g_lpart[split * SEQ + qbase + r0 + 8] = lsum1;
    }
}

// ============================================================================
// Kernel 3: combine splits.  out = (O0 + O1) / (l0 + l1)
// ============================================================================
__global__ __launch_bounds__(256)
void combine_kernel(float* __restrict__ out)
{
    int idx = blockIdx.x * 256 + threadIdx.x;
    int r = idx >> 5, c4 = (idx & 31) * 4;
    float inv = 1.f / (g_lpart[r] + g_lpart[SEQ + r]);
    float4 a = *(const float4*)&g_Opart[(size_t)r * DK + c4];
    float4 b = *(const float4*)&g_Opart[(size_t)(SEQ + r) * DK + c4];
    float4 o;
    o.x = (a.x + b.x) * inv; o.y = (a.y + b.y) * inv;
    o.z = (a.z + b.z) * inv; o.w = (a.w + b.w) * inv;
    *(float4*)&out[(size_t)r * DK + c4] = o;
}

// ---------------------------------------------------------------------------
extern "C" void kernel_launch(void* const* d_in, const int* in_sizes, int n_in,
                              void* d_out, int out_size)
{
    (void)in_sizes; (void)n_in; (void)out_size;
    const float* x  = (const float*)d_in[0];
    const float* Wq = (const float*)d_in[1];
    const float* bq = (const float*)d_in[2];
    const float* Wk = (const float*)d_in[3];
    const float* bk = (const float*)d_in[4];
    const float* Wv = (const float*)d_in[5];
    const float* bv = (const float*)d_in[6];
    float* out = (float*)d_out;

    cudaFuncSetAttribute(proj_tc_kernel,
                         cudaFuncAttributeMaxDynamicSharedMemorySize, PROJ_SMEM_B);
    cudaFuncSetAttribute(attn_kernel,
                         cudaFuncAttributeMaxDynamicSharedMemorySize, ATTN_SMEM_B);

    dim3 gProj(SEQ / 128, 1, 3);
    proj_tc_kernel<<<gProj, 256, PROJ_SMEM_B>>>(x, Wq, bq, Wk, bk, Wv, bv);

    dim3 gAttn(SEQ / 128, 2);
    attn_kernel<<<gAttn, 256, ATTN_SMEM_B>>>();

    combine_kernel<<<SEQ * DK / 4 / 256, 256>>>(out);
}

// round 14
// speedup vs baseline: 1.4488x; 1.4351x over previous
#include <cuda_runtime.h>
#include <cuda_fp16.h>
#include <cstdint>
#include <math.h>

#define SEQ 8192
#define DM  2048
#define DK  128

// Scratch (device globals: no allocation allowed)
__device__ float  g_Q[SEQ * DK];            // fp32 (rounded to fp16 at frag build)
__device__ __half g_Kh[SEQ * DK];           // fp16 K, [seq][dk]
__device__ __half g_Vth[DK * SEQ];          // fp16 V TRANSPOSED, [dk][seq]
__device__ float  g_Opart[2 * SEQ * DK];    // unnormalized partial O per split
__device__ float  g_lpart[2 * SEQ];         // partial row sums per split

// ===================== helpers =====================
__device__ __forceinline__ float ex2f(float x) {
    float y; asm("ex2.approx.ftz.f32 %0, %1;" : "=f"(y) : "f"(x)); return y;
}
__device__ __forceinline__ uint32_t smem_u32(const void* p) {
    uint32_t a;
    asm("{ .reg .u64 t; cvta.to.shared.u64 t, %1; cvt.u32.u64 %0, t; }" : "=r"(a) : "l"(p));
    return a;
}
__device__ __forceinline__ uint32_t h2(float lo, float hi) {
    __half2 h = __floats2half2_rn(lo, hi);
    return *reinterpret_cast<uint32_t*>(&h);
}
// mma.sync m16n8k16 f16 (fp32 accumulate): D = A*B + D   (baseline PTX)
__device__ __forceinline__ void mma16(float& c0, float& c1, float& c2, float& c3,
                                      uint32_t a0, uint32_t a1, uint32_t a2, uint32_t a3,
                                      uint32_t b0, uint32_t b1) {
    asm volatile("mma.sync.aligned.m16n8k16.row.col.f32.f16.f16.f32 "
                 "{%0,%1,%2,%3}, {%4,%5,%6,%7}, {%8,%9}, {%0,%1,%2,%3};"
                 : "+f"(c0), "+f"(c1), "+f"(c2), "+f"(c3)
                 : "r"(a0), "r"(a1), "r"(a2), "r"(a3), "r"(b0), "r"(b1));
}
#define CP_ASYNC16(saddr, gaddr) \
    asm volatile("cp.async.cg.shared.global [%0], [%1], 16;" :: "r"(saddr), "l"(gaddr))
#define CP_COMMIT()  asm volatile("cp.async.commit_group;" ::: "memory")
#define CP_WAIT1()   asm volatile("cp.async.wait_group 1;" ::: "memory")
#define CP_WAIT0()   asm volatile("cp.async.wait_group 0;" ::: "memory")

// ============================================================================
// Kernel 1: fp16 mma.sync QKV projection.  out = x @ W^T + b
//   grid (64,1,3), 256 thr = 8 warps 4(M)x2(N); BK=32 (2 k16 steps), double buf.
//   z=0 -> Q (fp32 out), z=1 -> K (fp16 out), z=2 -> V (fp16 TRANSPOSED out).
//   smem half tiles stride 40 (conflict-free: bank = 4g+q).
// ============================================================================
#define PH_STRIDE 40
#define PBUF_H (128 * PH_STRIDE)                 // halves per buffer per array
#define PROJ_SMEM_B (4 * PBUF_H * 2)             // xs[2]+ws[2] = 40960 bytes
// V-transpose staging: 128 x 136 halves = 34816 B  (reuses the same smem)
#define PSTG_STRIDE 136

__global__ __launch_bounds__(256)
void proj_tc_kernel(const float* __restrict__ x,
                    const float* __restrict__ Wq, const float* __restrict__ bq,
                    const float* __restrict__ Wk, const float* __restrict__ bk,
                    const float* __restrict__ Wv, const float* __restrict__ bv)
{
    const float* W; const float* bias;
    if (blockIdx.z == 0)      { W = Wq; bias = bq; }
    else if (blockIdx.z == 1) { W = Wk; bias = bk; }
    else                      { W = Wv; bias = bv; }

    extern __shared__ __half psm[];
    __half* xs = psm;                  // [2][128][40]
    __half* ws = psm + 2 * PBUF_H;     // [2][128][40]

    const int tid  = threadIdx.x;
    const int wid  = tid >> 5;
    const int lane = tid & 31;
    const int gid  = lane >> 2;
    const int qid  = lane & 3;
    const int wr   = wid & 3;
    const int wc   = wid >> 2;
    const int rowBase = blockIdx.x * 128;

    float o[2][8][4];
    #pragma unroll
    for (int mi = 0; mi < 2; mi++)
        #pragma unroll
        for (int j = 0; j < 8; j++)
            #pragma unroll
            for (int i = 0; i < 4; i++) o[mi][j][i] = 0.f;

    float4 xr[4], wrg[4];

    // prologue: K-tile 0 (global fp32 -> fp16 smem)
    #pragma unroll
    for (int l = 0; l < 4; l++) {
        int idx = tid + l * 256;
        int r = idx >> 3, q = (idx & 7) * 4;
        xr[l]  = *(const float4*)&x[(size_t)(rowBase + r) * DM + q];
        wrg[l] = *(const float4*)&W[(size_t)r * DM + q];
    }
    #pragma unroll
    for (int l = 0; l < 4; l++) {
        int idx = tid + l * 256;
        int r = idx >> 3, q = (idx & 7) * 4;
        uint2 u; u.x = h2(xr[l].x, xr[l].y); u.y = h2(xr[l].z, xr[l].w);
        *(uint2*)&xs[r * PH_STRIDE + q] = u;
        uint2 v; v.x = h2(wrg[l].x, wrg[l].y); v.y = h2(wrg[l].z, wrg[l].w);
        *(uint2*)&ws[r * PH_STRIDE + q] = v;
    }
    __syncthreads();

    const int arow0 = wr * 32 + gid;
    const int arow1 = wr * 32 + 16 + gid;

    for (int t = 0; t < 64; t++) {
        if (t < 63) {
            const int k0 = (t + 1) * 32;
            #pragma unroll
            for (int l = 0; l < 4; l++) {
                int idx = tid + l * 256;
                int r = idx >> 3, q = (idx & 7) * 4;
                xr[l]  = *(const float4*)&x[(size_t)(rowBase + r) * DM + k0 + q];
                wrg[l] = *(const float4*)&W[(size_t)r * DM + k0 + q];
            }
        }

        const __half* xb = xs + (t & 1) * PBUF_H;
        const __half* wb = ws + (t & 1) * PBUF_H;

        #pragma unroll
        for (int ks = 0; ks < 2; ks++) {
            const int k = ks * 16 + 2 * qid;
            uint32_t a[2][4];
            a[0][0] = *(const uint32_t*)&xb[arow0       * PH_STRIDE + k];
            a[0][1] = *(const uint32_t*)&xb[(arow0 + 8) * PH_STRIDE + k];
            a[0][2] = *(const uint32_t*)&xb[arow0       * PH_STRIDE + k + 8];
            a[0][3] = *(const uint32_t*)&xb[(arow0 + 8) * PH_STRIDE + k + 8];
            a[1][0] = *(const uint32_t*)&xb[arow1       * PH_STRIDE + k];
            a[1][1] = *(const uint32_t*)&xb[(arow1 + 8) * PH_STRIDE + k];
            a[1][2] = *(const uint32_t*)&xb[arow1       * PH_STRIDE + k + 8];
            a[1][3] = *(const uint32_t*)&xb[(arow1 + 8) * PH_STRIDE + k + 8];
            #pragma unroll
            for (int j = 0; j < 8; j++) {
                int n = wc * 64 + 8 * j + gid;
                uint32_t b0 = *(const uint32_t*)&wb[n * PH_STRIDE + k];
                uint32_t b1 = *(const uint32_t*)&wb[n * PH_STRIDE + k + 8];
                mma16(o[0][j][0], o[0][j][1], o[0][j][2], o[0][j][3],
                      a[0][0], a[0][1], a[0][2], a[0][3], b0, b1);
                mma16(o[1][j][0], o[1][j][1], o[1][j][2], o[1][j][3],
                      a[1][0], a[1][1], a[1][2], a[1][3], b0, b1);
            }
        }

        if (t < 63) {
            __half* xn = xs + ((t + 1) & 1) * PBUF_H;
            __half* wn = ws + ((t + 1) & 1) * PBUF_H;
            #pragma unroll
            for (int l = 0; l < 4; l++) {
                int idx = tid + l * 256;
                int r = idx >> 3, q = (idx & 7) * 4;
                uint2 u; u.x = h2(xr[l].x, xr[l].y); u.y = h2(xr[l].z, xr[l].w);
                *(uint2*)&xn[r * PH_STRIDE + q] = u;
                uint2 v; v.x = h2(wrg[l].x, wrg[l].y); v.y = h2(wrg[l].z, wrg[l].w);
                *(uint2*)&wn[r * PH_STRIDE + q] = v;
            }
        }
        __syncthreads();
    }

    // ---------------- epilogue ----------------
    if (blockIdx.z == 0) {
        // Q: fp32, direct
        #pragma unroll
        for (int mi = 0; mi < 2; mi++) {
            int row = rowBase + wr * 32 + mi * 16 + gid;
            #pragma unroll
            for (int j = 0; j < 8; j++) {
                int col = wc * 64 + 8 * j + 2 * qid;
                float2 bb = *(const float2*)&bias[col];
                *(float2*)&g_Q[(size_t)row * DK + col] =
                    make_float2(o[mi][j][0] + bb.x, o[mi][j][1] + bb.y);
                *(float2*)&g_Q[(size_t)(row + 8) * DK + col] =
                    make_float2(o[mi][j][2] + bb.x, o[mi][j][3] + bb.y);
            }
        }
    } else if (blockIdx.z == 1) {
        // K: fp16, direct [seq][dk]
        #pragma unroll
        for (int mi = 0; mi < 2; mi++) {
            int row = rowBase + wr * 32 + mi * 16 + gid;
            #pragma unroll
            for (int j = 0; j < 8; j++) {
                int col = wc * 64 + 8 * j + 2 * qid;
                float2 bb = *(const float2*)&bias[col];
                *(uint32_t*)&g_Kh[(size_t)row * DK + col] =
                    h2(o[mi][j][0] + bb.x, o[mi][j][1] + bb.y);
                *(uint32_t*)&g_Kh[(size_t)(row + 8) * DK + col] =
                    h2(o[mi][j][2] + bb.x, o[mi][j][3] + bb.y);
            }
        }
    } else {
        // V: stage fp16 tile in smem, then transposed coalesced write [dk][seq]
        __half* stg = psm;   // [128][136] halves = 34816 B (fits in 40960)
        __syncthreads();     // main-loop smem reads done
        #pragma unroll
        for (int mi = 0; mi < 2; mi++) {
            int row = wr * 32 + mi * 16 + gid;
            #pragma unroll
            for (int j = 0; j < 8; j++) {
                int col = wc * 64 + 8 * j + 2 * qid;
                float2 bb = *(const float2*)&bias[col];
                *(uint32_t*)&stg[row * PSTG_STRIDE + col] =
                    h2(o[mi][j][0] + bb.x, o[mi][j][1] + bb.y);
                *(uint32_t*)&stg[(row + 8) * PSTG_STRIDE + col] =
                    h2(o[mi][j][2] + bb.x, o[mi][j][3] + bb.y);
            }
        }
        __syncthreads();
        // write transposed: for each d (col), rows are contiguous in g_Vth
        for (int idx = tid; idx < 128 * 64; idx += 256) {
            int d = idx >> 6, rp = idx & 63;            // rp = row pair
            __half lo = stg[(2 * rp)     * PSTG_STRIDE + d];
            __half hi = stg[(2 * rp + 1) * PSTG_STRIDE + d];
            __half2 p = __halves2half2(lo, hi);
            *(uint32_t*)&g_Vth[(size_t)d * SEQ + rowBase + 2 * rp] =
                *reinterpret_cast<uint32_t*>(&p);
        }
    }
}

// ============================================================================
// Kernel 2: fp16 mma.sync flash attention, split-KV x2, cp.async double-buffer.
//   grid (64, 2), 256 thr = 8 warps x 16 Q rows.  KV tile 64.
//   QK: A=Q regs (8 k16 steps), B=K smem [kv][dk] stride 136.
//   PV: A=P smem [q][kv] stride 72, B=Vt smem [dk][kv] stride 72.
//   All banks: 4g+q, conflict-free.  Softmax fp32, no max-subtraction.
// ============================================================================
#define KS_STRIDE 136
#define VT_STRIDE 72
#define PS_STRIDE 72
#define KV_BUF_H  (64 * KS_STRIDE + 128 * VT_STRIDE)   // 17920 halves / buffer
#define VT_OFF_H  (64 * KS_STRIDE)                     // 8704
#define P_H       (2 * KV_BUF_H)                       // 35840
#define ATTN_SMEM_B ((P_H + 128 * PS_STRIDE) * 2)      // 90112 bytes

__global__ __launch_bounds__(256)
void attn_kernel()
{
    extern __shared__ __half smh[];
    const uint32_t smb = smem_u32(smh);
    const int tid  = threadIdx.x;
    const int wid  = tid >> 5;
    const int lane = tid & 31;
    const int gid  = lane >> 2;
    const int qid  = lane & 3;
    const int qbase = blockIdx.x * 128;
    const int split = blockIdx.y;
    const int r0 = (wid << 4) + gid;
    const int kvbase = split * 4096;

    // --- Q fragments (fp16) in registers, pre-scaled by log2e/sqrt(dk) ---
    const float qscale = 1.4426950408889634f * 0.08838834764831845f;
    uint32_t qf[8][4];
    {
        const float* q0 = &g_Q[(size_t)(qbase + r0) * DK];
        const float* q1 = &g_Q[(size_t)(qbase + r0 + 8) * DK];
        #pragma unroll
        for (int ks = 0; ks < 8; ks++) {
            const int k = ks * 16 + 2 * qid;
            qf[ks][0] = h2(q0[k]     * qscale, q0[k + 1] * qscale);
            qf[ks][1] = h2(q1[k]     * qscale, q1[k + 1] * qscale);
            qf[ks][2] = h2(q0[k + 8] * qscale, q0[k + 9] * qscale);
            qf[ks][3] = h2(q1[k + 8] * qscale, q1[k + 9] * qscale);
        }
    }

    float o[16][4];
    #pragma unroll
    for (int j = 0; j < 16; j++)
        #pragma unroll
        for (int i = 0; i < 4; i++) o[j][i] = 0.f;
    float lsum0 = 0.f, lsum1 = 0.f;

    auto issue_tile = [&](int t, int b) {
        const int kv0 = kvbase + t * 64;
        const uint32_t bb = smb + (uint32_t)(b * KV_BUF_H) * 2u;
        #pragma unroll
        for (int l = 0; l < 8; l++) {
            int idx = tid + l * 256;                 // 0..2047
            if (idx < 1024) {                        // K tile: 64 rows x 256 B
                int r = idx >> 4, c = idx & 15;
                CP_ASYNC16(bb + (uint32_t)(r * KS_STRIDE * 2 + c * 16),
                           &g_Kh[(size_t)(kv0 + r) * DK + c * 8]);
            } else {                                 // Vt tile: 128 rows x 128 B
                int v = idx - 1024;
                int d = v >> 3, c = v & 7;
                CP_ASYNC16(bb + (uint32_t)(VT_OFF_H * 2 + d * VT_STRIDE * 2 + c * 16),
                           &g_Vth[(size_t)d * SEQ + kv0 + c * 8]);
            }
        }
        CP_COMMIT();
    };

    issue_tile(0, 0);

    for (int t = 0; t < 64; t++) {
        if (t < 63) { issue_tile(t + 1, (t + 1) & 1); CP_WAIT1(); }
        else        { CP_WAIT0(); }
        __syncthreads();

        const __half* kb = smh + (t & 1) * KV_BUF_H;
        const __half* vb = kb + VT_OFF_H;

        // ---- S = Q K^T ----
        float s[8][4];
        #pragma unroll
        for (int j = 0; j < 8; j++)
            #pragma unroll
            for (int i = 0; i < 4; i++) s[j][i] = 0.f;

        #pragma unroll
        for (int ks = 0; ks < 8; ks++) {
            const int k = ks * 16 + 2 * qid;
            #pragma unroll
            for (int j = 0; j < 8; j++) {
                const int n = 8 * j + gid;
                uint32_t b0 = *(const uint32_t*)&kb[n * KS_STRIDE + k];
                uint32_t b1 = *(const uint32_t*)&kb[n * KS_STRIDE + k + 8];
                mma16(s[j][0], s[j][1], s[j][2], s[j][3],
                      qf[ks][0], qf[ks][1], qf[ks][2], qf[ks][3], b0, b1);
            }
        }

        // ---- softmax (exp2; Q pre-scaled), quad rowsums ----
        float ps0 = 0.f, ps1 = 0.f;
        #pragma unroll
        for (int j = 0; j < 8; j++) {
            s[j][0] = ex2f(s[j][0]); s[j][1] = ex2f(s[j][1]);
            s[j][2] = ex2f(s[j][2]); s[j][3] = ex2f(s[j][3]);
            ps0 += s[j][0] + s[j][1];
            ps1 += s[j][2] + s[j][3];
        }
        ps0 += __shfl_xor_sync(0xffffffffu, ps0, 1);
        ps0 += __shfl_xor_sync(0xffffffffu, ps0, 2);
        ps1 += __shfl_xor_sync(0xffffffffu, ps1, 1);
        ps1 += __shfl_xor_sync(0xffffffffu, ps1, 2);
        lsum0 += ps0; lsum1 += ps1;

        // ---- P -> smem (fp16 half2, k-contiguous pairs), warp-private rows ----
        __half* Ps = smh + P_H;
        #pragma unroll
        for (int j = 0; j < 8; j++) {
            const int col = 8 * j + 2 * qid;
            *(uint32_t*)&Ps[r0       * PS_STRIDE + col] = h2(s[j][0], s[j][1]);
            *(uint32_t*)&Ps[(r0 + 8) * PS_STRIDE + col] = h2(s[j][2], s[j][3]);
        }
        __syncwarp();

        // ---- O += P V  (A = P rows, B = Vt cols) ----
        #pragma unroll
        for (int ks = 0; ks < 4; ks++) {
            const int k = ks * 16 + 2 * qid;
            uint32_t a0 = *(const uint32_t*)&Ps[r0       * PS_STRIDE + k];
            uint32_t a1 = *(const uint32_t*)&Ps[(r0 + 8) * PS_STRIDE + k];
            uint32_t a2 = *(const uint32_t*)&Ps[r0       * PS_STRIDE + k + 8];
            uint32_t a3 = *(const uint32_t*)&Ps[(r0 + 8) * PS_STRIDE + k + 8];
            #pragma unroll
            for (int j = 0; j < 16; j++) {
                const int d = 8 * j + gid;
                uint32_t b0 = *(const uint32_t*)&vb[d * VT_STRIDE + k];
                uint32_t b1 = *(const uint32_t*)&vb[d * VT_STRIDE + k + 8];
                mma16(o[j][0], o[j][1], o[j][2], o[j][3], a0, a1, a2, a3, b0, b1);
            }
        }
        __syncthreads();   // KV buffer free for re-issue; P free for next tile
    }

    // ---- epilogue: unnormalized partials ----
    float* Op = g_Opart + (size_t)split * SEQ * DK;
    #pragma unroll
    for (int j = 0; j < 16; j++) {
        int col = 8 * j + 2 * qid;
        *(float2*)&Op[(size_t)(qbase + r0) * DK + col]     = make_float2(o[j][0], o[j][1]);
        *(float2*)&Op[(size_t)(qbase + r0 + 8) * DK + col] = make_float2(o[j][2], o[j][3]);
    }
    if (qid == 0) {
        g_lpart[split * SEQ + qbase + r0]     = lsum0;
        g_lpart[split * SEQ + qbase + r0 + 8] = lsum1;
    }
}

// ============================================================================
// Kernel 3: combine splits.  out = (O0 + O1) / (l0 + l1)
// ============================================================================
__global__ __launch_bounds__(256)
void combine_kernel(float* __restrict__ out)
{
    int idx = blockIdx.x * 256 + threadIdx.x;
    int r = idx >> 5, c4 = (idx & 31) * 4;
    float inv = 1.f / (g_lpart[r] + g_lpart[SEQ + r]);
    float4 a = *(const float4*)&g_Opart[(size_t)r * DK + c4];
    float4 b = *(const float4*)&g_Opart[(size_t)(SEQ + r) * DK + c4];
    float4 o;
    o.x = (a.x + b.x) * inv; o.y = (a.y + b.y) * inv;
    o.z = (a.z + b.z) * inv; o.w = (a.w + b.w) * inv;
    *(float4*)&out[(size_t)r * DK + c4] = o;
}

// ---------------------------------------------------------------------------
extern "C" void kernel_launch(void* const* d_in, const int* in_sizes, int n_in,
                              void* d_out, int out_size)
{
    (void)in_sizes; (void)n_in; (void)out_size;
    const float* x  = (const float*)d_in[0];
    const float* Wq = (const float*)d_in[1];
    const float* bq = (const float*)d_in[2];
    const float* Wk = (const float*)d_in[3];
    const float* bk = (const float*)d_in[4];
    const float* Wv = (const float*)d_in[5];
    const float* bv = (const float*)d_in[6];
    float* out = (float*)d_out;

    cudaFuncSetAttribute(proj_tc_kernel,
                         cudaFuncAttributeMaxDynamicSharedMemorySize, PROJ_SMEM_B);
    cudaFuncSetAttribute(attn_kernel,
                         cudaFuncAttributeMaxDynamicSharedMemorySize, ATTN_SMEM_B);

    dim3 gProj(SEQ / 128, 1, 3);
    proj_tc_kernel<<<gProj, 256, PROJ_SMEM_B>>>(x, Wq, bq, Wk, bk, Wv, bv);

    dim3 gAttn(SEQ / 128, 2);
    attn_kernel<<<gAttn, 256, ATTN_SMEM_B>>>();

    combine_kernel<<<SEQ * DK / 4 / 256, 256>>>(out);
}

// round 16
// speedup vs baseline: 1.6339x; 1.1278x over previous
#include <cuda_runtime.h>
#include <cuda_fp16.h>
#include <cstdint>
#include <math.h>

#define SEQ 8192
#define DM  2048
#define DK  128

// Scratch (device globals: no allocation allowed)
__device__ float  g_Q[SEQ * DK];            // fp32 Q
__device__ __half g_Kh[SEQ * DK];           // fp16 K, [seq][dk]
__device__ __half g_Vth[DK * SEQ];          // fp16 V TRANSPOSED, [dk][seq]
__device__ __half g_xh[SEQ * DM];           // fp16 x
__device__ __half g_Wqh[DK * DM];           // fp16 weights
__device__ __half g_Wkh[DK * DM];
__device__ __half g_Wvh[DK * DM];
__device__ float  g_Opart[2 * SEQ * DK];    // unnormalized partial O per split
__device__ float  g_lpart[2 * SEQ];         // partial row sums per split

// ===================== helpers =====================
__device__ __forceinline__ float ex2f(float x) {
    float y; asm("ex2.approx.ftz.f32 %0, %1;" : "=f"(y) : "f"(x)); return y;
}
__device__ __forceinline__ uint32_t smem_u32(const void* p) {
    uint32_t a;
    asm("{ .reg .u64 t; cvta.to.shared.u64 t, %1; cvt.u32.u64 %0, t; }" : "=r"(a) : "l"(p));
    return a;
}
__device__ __forceinline__ uint32_t h2(float lo, float hi) {
    __half2 h = __floats2half2_rn(lo, hi);
    return *reinterpret_cast<uint32_t*>(&h);
}
// mma.sync m16n8k16 f16 (fp32 accumulate): D = A*B + D
__device__ __forceinline__ void mma16(float& c0, float& c1, float& c2, float& c3,
                                      uint32_t a0, uint32_t a1, uint32_t a2, uint32_t a3,
                                      uint32_t b0, uint32_t b1) {
    asm volatile("mma.sync.aligned.m16n8k16.row.col.f32.f16.f16.f32 "
                 "{%0,%1,%2,%3}, {%4,%5,%6,%7}, {%8,%9}, {%0,%1,%2,%3};"
                 : "+f"(c0), "+f"(c1), "+f"(c2), "+f"(c3)
                 : "r"(a0), "r"(a1), "r"(a2), "r"(a3), "r"(b0), "r"(b1));
}
#define CP_ASYNC16(saddr, gaddr) \
    asm volatile("cp.async.cg.shared.global [%0], [%1], 16;" :: "r"(saddr), "l"(gaddr))
#define CP_COMMIT()  asm volatile("cp.async.commit_group;" ::: "memory")
#define CP_WAIT1()   asm volatile("cp.async.wait_group 1;" ::: "memory")
#define CP_WAIT0()   asm volatile("cp.async.wait_group 0;" ::: "memory")

// ============================================================================
// Kernel 0: fp32 -> fp16 convert (x and the three W's; RN rounding identical
// to the staging-time rounding it replaces).
// ============================================================================
__global__ __launch_bounds__(256)
void cvt_kernel(const float* __restrict__ src, __half* __restrict__ dst, int n4)
{
    int idx = blockIdx.x * 256 + threadIdx.x;
    if (idx >= n4) return;
    float4 v = *(const float4*)&src[idx * 4];
    uint2 u; u.x = h2(v.x, v.y); u.y = h2(v.z, v.w);
    *(uint2*)&dst[idx * 4] = u;
}

// ============================================================================
// Kernel 1: fp16 mma.sync QKV projection, pure cp.async + mma.
//   out = x @ W^T + b.  grid (64,1,3), 256 thr = 8 warps 4(M)x2(N).
//   BK=64 (4 k16 steps), 32 K-tiles, double-buffered fp16 smem, stride 72
//   (conflict-free: bank = 4g+q).  No staging/cvt in the main loop.
//   z=0 -> Q (fp32), z=1 -> K (fp16), z=2 -> V (fp16 transposed).
// ============================================================================
#define PH_STRIDE 72
#define PBUF_H (128 * PH_STRIDE)                 // 9216 halves per buffer/array
#define PROJ_SMEM_B (4 * PBUF_H * 2)             // xs[2]+ws[2] = 73728 bytes
#define PSTG_STRIDE 136                          // V-transpose staging

__global__ __launch_bounds__(256, 2)
void proj_tc_kernel(const float* __restrict__ bq,
                    const float* __restrict__ bk,
                    const float* __restrict__ bv)
{
    const __half* Wh; const float* bias;
    if (blockIdx.z == 0)      { Wh = g_Wqh; bias = bq; }
    else if (blockIdx.z == 1) { Wh = g_Wkh; bias = bk; }
    else                      { Wh = g_Wvh; bias = bv; }

    extern __shared__ __half psm[];
    __half* xs = psm;                  // [2][128][72]
    __half* ws = psm + 2 * PBUF_H;     // [2][128][72]
    const uint32_t smb = smem_u32(psm);

    const int tid  = threadIdx.x;
    const int wid  = tid >> 5;
    const int lane = tid & 31;
    const int gid  = lane >> 2;
    const int qid  = lane & 3;
    const int wr   = wid & 3;
    const int wc   = wid >> 2;
    const int rowBase = blockIdx.x * 128;

    float o[2][8][4];
    #pragma unroll
    for (int mi = 0; mi < 2; mi++)
        #pragma unroll
        for (int j = 0; j < 8; j++)
            #pragma unroll
            for (int i = 0; i < 4; i++) o[mi][j][i] = 0.f;

    auto issue_tile = [&](int t, int b) {
        const int k0 = t * 64;
        const uint32_t xb = smb + (uint32_t)(b * PBUF_H) * 2u;
        const uint32_t wb = smb + (uint32_t)((2 + b) * PBUF_H) * 2u;
        #pragma unroll
        for (int l = 0; l < 4; l++) {
            int idx = tid + l * 256;                 // 0..1023
            int r = idx >> 3, c = idx & 7;           // row, 8-half chunk
            CP_ASYNC16(xb + (uint32_t)(r * PH_STRIDE + c * 8) * 2u,
                       &g_xh[(size_t)(rowBase + r) * DM + k0 + c * 8]);
            CP_ASYNC16(wb + (uint32_t)(r * PH_STRIDE + c * 8) * 2u,
                       &Wh[(size_t)r * DM + k0 + c * 8]);
        }
        CP_COMMIT();
    };

    issue_tile(0, 0);

    const int arow0 = wr * 32 + gid;
    const int arow1 = wr * 32 + 16 + gid;

    for (int t = 0; t < 32; t++) {
        if (t < 31) { issue_tile(t + 1, (t + 1) & 1); CP_WAIT1(); }
        else        { CP_WAIT0(); }
        __syncthreads();

        const __half* xb = xs + (t & 1) * PBUF_H;
        const __half* wb = ws + (t & 1) * PBUF_H;

        #pragma unroll
        for (int ks = 0; ks < 4; ks++) {
            const int k = ks * 16 + 2 * qid;
            uint32_t a[2][4];
            a[0][0] = *(const uint32_t*)&xb[arow0       * PH_STRIDE + k];
            a[0][1] = *(const uint32_t*)&xb[(arow0 + 8) * PH_STRIDE + k];
            a[0][2] = *(const uint32_t*)&xb[arow0       * PH_STRIDE + k + 8];
            a[0][3] = *(const uint32_t*)&xb[(arow0 + 8) * PH_STRIDE + k + 8];
            a[1][0] = *(const uint32_t*)&xb[arow1       * PH_STRIDE + k];
            a[1][1] = *(const uint32_t*)&xb[(arow1 + 8) * PH_STRIDE + k];
            a[1][2] = *(const uint32_t*)&xb[arow1       * PH_STRIDE + k + 8];
            a[1][3] = *(const uint32_t*)&xb[(arow1 + 8) * PH_STRIDE + k + 8];
            #pragma unroll
            for (int j = 0; j < 8; j++) {
                int n = wc * 64 + 8 * j + gid;
                uint32_t b0 = *(const uint32_t*)&wb[n * PH_STRIDE + k];
                uint32_t b1 = *(const uint32_t*)&wb[n * PH_STRIDE + k + 8];
                mma16(o[0][j][0], o[0][j][1], o[0][j][2], o[0][j][3],
                      a[0][0], a[0][1], a[0][2], a[0][3], b0, b1);
                mma16(o[1][j][0], o[1][j][1], o[1][j][2], o[1][j][3],
                      a[1][0], a[1][1], a[1][2], a[1][3], b0, b1);
            }
        }
        __syncthreads();   // buffer reads done before re-issue
    }

    // ---------------- epilogue ----------------
    if (blockIdx.z == 0) {
        #pragma unroll
        for (int mi = 0; mi < 2; mi++) {
            int row = rowBase + wr * 32 + mi * 16 + gid;
            #pragma unroll
            for (int j = 0; j < 8; j++) {
                int col = wc * 64 + 8 * j + 2 * qid;
                float2 bb = *(const float2*)&bias[col];
                *(float2*)&g_Q[(size_t)row * DK + col] =
                    make_float2(o[mi][j][0] + bb.x, o[mi][j][1] + bb.y);
                *(float2*)&g_Q[(size_t)(row + 8) * DK + col] =
                    make_float2(o[mi][j][2] + bb.x, o[mi][j][3] + bb.y);
            }
        }
    } else if (blockIdx.z == 1) {
        #pragma unroll
        for (int mi = 0; mi < 2; mi++) {
            int row = rowBase + wr * 32 + mi * 16 + gid;
            #pragma unroll
            for (int j = 0; j < 8; j++) {
                int col = wc * 64 + 8 * j + 2 * qid;
                float2 bb = *(const float2*)&bias[col];
                *(uint32_t*)&g_Kh[(size_t)row * DK + col] =
                    h2(o[mi][j][0] + bb.x, o[mi][j][1] + bb.y);
                *(uint32_t*)&g_Kh[(size_t)(row + 8) * DK + col] =
                    h2(o[mi][j][2] + bb.x, o[mi][j][3] + bb.y);
            }
        }
    } else {
        __half* stg = psm;   // [128][136] halves = 34816 B (fits)
        __syncthreads();
        #pragma unroll
        for (int mi = 0; mi < 2; mi++) {
            int row = wr * 32 + mi * 16 + gid;
            #pragma unroll
            for (int j = 0; j < 8; j++) {
                int col = wc * 64 + 8 * j + 2 * qid;
                float2 bb = *(const float2*)&bias[col];
                *(uint32_t*)&stg[row * PSTG_STRIDE + col] =
                    h2(o[mi][j][0] + bb.x, o[mi][j][1] + bb.y);
                *(uint32_t*)&stg[(row + 8) * PSTG_STRIDE + col] =
                    h2(o[mi][j][2] + bb.x, o[mi][j][3] + bb.y);
            }
        }
        __syncthreads();
        for (int idx = tid; idx < 128 * 64; idx += 256) {
            int d = idx >> 6, rp = idx & 63;
            __half lo = stg[(2 * rp)     * PSTG_STRIDE + d];
            __half hi = stg[(2 * rp + 1) * PSTG_STRIDE + d];
            __half2 p = __halves2half2(lo, hi);
            *(uint32_t*)&g_Vth[(size_t)d * SEQ + rowBase + 2 * rp] =
                *reinterpret_cast<uint32_t*>(&p);
        }
    }
}

// ============================================================================
// Kernel 2: fp16 mma.sync flash attention (UNCHANGED from R14 pass).
// ============================================================================
#define KS_STRIDE 136
#define VT_STRIDE 72
#define PS_STRIDE 72
#define KV_BUF_H  (64 * KS_STRIDE + 128 * VT_STRIDE)   // 17920 halves / buffer
#define VT_OFF_H  (64 * KS_STRIDE)                     // 8704
#define P_H       (2 * KV_BUF_H)                       // 35840
#define ATTN_SMEM_B ((P_H + 128 * PS_STRIDE) * 2)      // 90112 bytes

__global__ __launch_bounds__(256)
void attn_kernel()
{
    extern __shared__ __half smh[];
    const uint32_t smb = smem_u32(smh);
    const int tid  = threadIdx.x;
    const int wid  = tid >> 5;
    const int lane = tid & 31;
    const int gid  = lane >> 2;
    const int qid  = lane & 3;
    const int qbase = blockIdx.x * 128;
    const int split = blockIdx.y;
    const int r0 = (wid << 4) + gid;
    const int kvbase = split * 4096;

    const float qscale = 1.4426950408889634f * 0.08838834764831845f;
    uint32_t qf[8][4];
    {
        const float* q0 = &g_Q[(size_t)(qbase + r0) * DK];
        const float* q1 = &g_Q[(size_t)(qbase + r0 + 8) * DK];
        #pragma unroll
        for (int ks = 0; ks < 8; ks++) {
            const int k = ks * 16 + 2 * qid;
            qf[ks][0] = h2(q0[k]     * qscale, q0[k + 1] * qscale);
            qf[ks][1] = h2(q1[k]     * qscale, q1[k + 1] * qscale);
            qf[ks][2] = h2(q0[k + 8] * qscale, q0[k + 9] * qscale);
            qf[ks][3] = h2(q1[k + 8] * qscale, q1[k + 9] * qscale);
        }
    }

    float o[16][4];
    #pragma unroll
    for (int j = 0; j < 16; j++)
        #pragma unroll
        for (int i = 0; i < 4; i++) o[j][i] = 0.f;
    float lsum0 = 0.f, lsum1 = 0.f;

    auto issue_tile = [&](int t, int b) {
        const int kv0 = kvbase + t * 64;
        const uint32_t bb = smb + (uint32_t)(b * KV_BUF_H) * 2u;
        #pragma unroll
        for (int l = 0; l < 8; l++) {
            int idx = tid + l * 256;
            if (idx < 1024) {
                int r = idx >> 4, c = idx & 15;
                CP_ASYNC16(bb + (uint32_t)(r * KS_STRIDE * 2 + c * 16),
                           &g_Kh[(size_t)(kv0 + r) * DK + c * 8]);
            } else {
                int v = idx - 1024;
                int d = v >> 3, c = v & 7;
                CP_ASYNC16(bb + (uint32_t)(VT_OFF_H * 2 + d * VT_STRIDE * 2 + c * 16),
                           &g_Vth[(size_t)d * SEQ + kv0 + c * 8]);
            }
        }
        CP_COMMIT();
    };

    issue_tile(0, 0);

    for (int t = 0; t < 64; t++) {
        if (t < 63) { issue_tile(t + 1, (t + 1) & 1); CP_WAIT1(); }
        else        { CP_WAIT0(); }
        __syncthreads();

        const __half* kb = smh + (t & 1) * KV_BUF_H;
        const __half* vb = kb + VT_OFF_H;

        float s[8][4];
        #pragma unroll
        for (int j = 0; j < 8; j++)
            #pragma unroll
            for (int i = 0; i < 4; i++) s[j][i] = 0.f;

        #pragma unroll
        for (int ks = 0; ks < 8; ks++) {
            const int k = ks * 16 + 2 * qid;
            #pragma unroll
            for (int j = 0; j < 8; j++) {
                const int n = 8 * j + gid;
                uint32_t b0 = *(const uint32_t*)&kb[n * KS_STRIDE + k];
                uint32_t b1 = *(const uint32_t*)&kb[n * KS_STRIDE + k + 8];
                mma16(s[j][0], s[j][1], s[j][2], s[j][3],
                      qf[ks][0], qf[ks][1], qf[ks][2], qf[ks][3], b0, b1);
            }
        }

        float ps0 = 0.f, ps1 = 0.f;
        #pragma unroll
        for (int j = 0; j < 8; j++) {
            s[j][0] = ex2f(s[j][0]); s[j][1] = ex2f(s[j][1]);
            s[j][2] = ex2f(s[j][2]); s[j][3] = ex2f(s[j][3]);
            ps0 += s[j][0] + s[j][1];
            ps1 += s[j][2] + s[j][3];
        }
        ps0 += __shfl_xor_sync(0xffffffffu, ps0, 1);
        ps0 += __shfl_xor_sync(0xffffffffu, ps0, 2);
        ps1 += __shfl_xor_sync(0xffffffffu, ps1, 1);
        ps1 += __shfl_xor_sync(0xffffffffu, ps1, 2);
        lsum0 += ps0; lsum1 += ps1;

        __half* Ps = smh + P_H;
        #pragma unroll
        for (int j = 0; j < 8; j++) {
            const int col = 8 * j + 2 * qid;
            *(uint32_t*)&Ps[r0       * PS_STRIDE + col] = h2(s[j][0], s[j][1]);
            *(uint32_t*)&Ps[(r0 + 8) * PS_STRIDE + col] = h2(s[j][2], s[j][3]);
        }
        __syncwarp();

        #pragma unroll
        for (int ks = 0; ks < 4; ks++) {
            const int k = ks * 16 + 2 * qid;
            uint32_t a0 = *(const uint32_t*)&Ps[r0       * PS_STRIDE + k];
            uint32_t a1 = *(const uint32_t*)&Ps[(r0 + 8) * PS_STRIDE + k];
            uint32_t a2 = *(const uint32_t*)&Ps[r0       * PS_STRIDE + k + 8];
            uint32_t a3 = *(const uint32_t*)&Ps[(r0 + 8) * PS_STRIDE + k + 8];
            #pragma unroll
            for (int j = 0; j < 16; j++) {
                const int d = 8 * j + gid;
                uint32_t b0 = *(const uint32_t*)&vb[d * VT_STRIDE + k];
                uint32_t b1 = *(const uint32_t*)&vb[d * VT_STRIDE + k + 8];
                mma16(o[j][0], o[j][1], o[j][2], o[j][3], a0, a1, a2, a3, b0, b1);
            }
        }
        __syncthreads();
    }

    float* Op = g_Opart + (size_t)split * SEQ * DK;
    #pragma unroll
    for (int j = 0; j < 16; j++) {
        int col = 8 * j + 2 * qid;
        *(float2*)&Op[(size_t)(qbase + r0) * DK + col]     = make_float2(o[j][0], o[j][1]);
        *(float2*)&Op[(size_t)(qbase + r0 + 8) * DK + col] = make_float2(o[j][2], o[j][3]);
    }
    if (qid == 0) {
        g_lpart[split * SEQ + qbase + r0]     = lsum0;
        g_lpart[split * SEQ + qbase + r0 + 8] = lsum1;
    }
}

// ============================================================================
// Kernel 3: combine splits.  out = (O0 + O1) / (l0 + l1)
// ============================================================================
__global__ __launch_bounds__(256)
void combine_kernel(float* __restrict__ out)
{
    int idx = blockIdx.x * 256 + threadIdx.x;
    int r = idx >> 5, c4 = (idx & 31) * 4;
    float inv = 1.f / (g_lpart[r] + g_lpart[SEQ + r]);
    float4 a = *(const float4*)&g_Opart[(size_t)r * DK + c4];
    float4 b = *(const float4*)&g_Opart[(size_t)(SEQ + r) * DK + c4];
    float4 o;
    o.x = (a.x + b.x) * inv; o.y = (a.y + b.y) * inv;
    o.z = (a.z + b.z) * inv; o.w = (a.w + b.w) * inv;
    *(float4*)&out[(size_t)r * DK + c4] = o;
}

// ---------------------------------------------------------------------------
extern "C" void kernel_launch(void* const* d_in, const int* in_sizes, int n_in,
                              void* d_out, int out_size)
{
    (void)in_sizes; (void)n_in; (void)out_size;
    const float* x  = (const float*)d_in[0];
    const float* Wq = (const float*)d_in[1];
    const float* bq = (const float*)d_in[2];
    const float* Wk = (const float*)d_in[3];
    const float* bk = (const float*)d_in[4];
    const float* Wv = (const float*)d_in[5];
    const float* bv = (const float*)d_in[6];
    float* out = (float*)d_out;

    cudaFuncSetAttribute(proj_tc_kernel,
                         cudaFuncAttributeMaxDynamicSharedMemorySize, PROJ_SMEM_B);
    cudaFuncSetAttribute(attn_kernel,
                         cudaFuncAttributeMaxDynamicSharedMemorySize, ATTN_SMEM_B);

    // fp32 -> fp16 conversion (x and weights)
    __half *d_xh, *d_wqh, *d_wkh, *d_wvh;
    cudaGetSymbolAddress((void**)&d_xh,  g_xh);
    cudaGetSymbolAddress((void**)&d_wqh, g_Wqh);
    cudaGetSymbolAddress((void**)&d_wkh, g_Wkh);
    cudaGetSymbolAddress((void**)&d_wvh, g_Wvh);
    const int n4x = SEQ * DM / 4;        // 4194304
    const int n4w = DK * DM / 4;         // 65536
    cvt_kernel<<<(n4x + 255) / 256, 256>>>(x,  d_xh,  n4x);
    cvt_kernel<<<(n4w + 255) / 256, 256>>>(Wq, d_wqh, n4w);
    cvt_kernel<<<(n4w + 255) / 256, 256>>>(Wk, d_wkh, n4w);
    cvt_kernel<<<(n4w + 255) / 256, 256>>>(Wv, d_wvh, n4w);

    dim3 gProj(SEQ / 128, 1, 3);
    proj_tc_kernel<<<gProj, 256, PROJ_SMEM_B>>>(bq, bk, bv);

    dim3 gAttn(SEQ / 128, 2);
    attn_kernel<<<gAttn, 256, ATTN_SMEM_B>>>();

    combine_kernel<<<SEQ * DK / 4 / 256, 256>>>(out);
}

// round 17
// speedup vs baseline: 1.7352x; 1.0620x over previous
#include <cuda_runtime.h>
#include <cuda_fp16.h>
#include <cstdint>
#include <math.h>

#define SEQ 8192
#define DM  2048
#define DK  128

// Scratch (device globals: no allocation allowed)
__device__ float  g_Q[SEQ * DK];            // fp32 Q
__device__ __half g_Kh[SEQ * DK];           // fp16 K, [seq][dk]
__device__ __half g_Vth[DK * SEQ];          // fp16 V TRANSPOSED, [dk][seq]
__device__ __half g_xh[SEQ * DM];           // fp16 x
__device__ __half g_Wqh[DK * DM];           // fp16 weights
__device__ __half g_Wkh[DK * DM];
__device__ __half g_Wvh[DK * DM];
__device__ float  g_Opart[2 * SEQ * DK];    // unnormalized partial O per split
__device__ float  g_lpart[2 * SEQ];         // partial row sums per split

// ===================== helpers =====================
__device__ __forceinline__ float ex2f(float x) {
    float y; asm("ex2.approx.ftz.f32 %0, %1;" : "=f"(y) : "f"(x)); return y;
}
__device__ __forceinline__ uint32_t smem_u32(const void* p) {
    uint32_t a;
    asm("{ .reg .u64 t; cvta.to.shared.u64 t, %1; cvt.u32.u64 %0, t; }" : "=r"(a) : "l"(p));
    return a;
}
__device__ __forceinline__ uint32_t h2(float lo, float hi) {
    __half2 h = __floats2half2_rn(lo, hi);
    return *reinterpret_cast<uint32_t*>(&h);
}
// mma.sync m16n8k16 f16 (fp32 accumulate): D = A*B + D
__device__ __forceinline__ void mma16(float& c0, float& c1, float& c2, float& c3,
                                      uint32_t a0, uint32_t a1, uint32_t a2, uint32_t a3,
                                      uint32_t b0, uint32_t b1) {
    asm volatile("mma.sync.aligned.m16n8k16.row.col.f32.f16.f16.f32 "
                 "{%0,%1,%2,%3}, {%4,%5,%6,%7}, {%8,%9}, {%0,%1,%2,%3};"
                 : "+f"(c0), "+f"(c1), "+f"(c2), "+f"(c3)
                 : "r"(a0), "r"(a1), "r"(a2), "r"(a3), "r"(b0), "r"(b1));
}
#define CP_ASYNC16(saddr, gaddr) \
    asm volatile("cp.async.cg.shared.global [%0], [%1], 16;" :: "r"(saddr), "l"(gaddr))
#define CP_COMMIT()  asm volatile("cp.async.commit_group;" ::: "memory")
#define CP_WAIT1()   asm volatile("cp.async.wait_group 1;" ::: "memory")
#define CP_WAIT0()   asm volatile("cp.async.wait_group 0;" ::: "memory")

// ============================================================================
// Kernel 0: fp32 -> fp16 convert (UNCHANGED from R16 pass).
// ============================================================================
__global__ __launch_bounds__(256)
void cvt_kernel(const float* __restrict__ src, __half* __restrict__ dst, int n4)
{
    int idx = blockIdx.x * 256 + threadIdx.x;
    if (idx >= n4) return;
    float4 v = *(const float4*)&src[idx * 4];
    uint2 u; u.x = h2(v.x, v.y); u.y = h2(v.z, v.w);
    *(uint2*)&dst[idx * 4] = u;
}

// ============================================================================
// Kernel 1: fp16 mma.sync QKV projection (UNCHANGED from R16 pass).
// ============================================================================
#define PH_STRIDE 72
#define PBUF_H (128 * PH_STRIDE)
#define PROJ_SMEM_B (4 * PBUF_H * 2)             // 73728 bytes
#define PSTG_STRIDE 136

__global__ __launch_bounds__(256, 2)
void proj_tc_kernel(const float* __restrict__ bq,
                    const float* __restrict__ bk,
                    const float* __restrict__ bv)
{
    const __half* Wh; const float* bias;
    if (blockIdx.z == 0)      { Wh = g_Wqh; bias = bq; }
    else if (blockIdx.z == 1) { Wh = g_Wkh; bias = bk; }
    else                      { Wh = g_Wvh; bias = bv; }

    extern __shared__ __half psm[];
    __half* xs = psm;                  // [2][128][72]
    __half* ws = psm + 2 * PBUF_H;     // [2][128][72]
    const uint32_t smb = smem_u32(psm);

    const int tid  = threadIdx.x;
    const int wid  = tid >> 5;
    const int lane = tid & 31;
    const int gid  = lane >> 2;
    const int qid  = lane & 3;
    const int wr   = wid & 3;
    const int wc   = wid >> 2;
    const int rowBase = blockIdx.x * 128;

    float o[2][8][4];
    #pragma unroll
    for (int mi = 0; mi < 2; mi++)
        #pragma unroll
        for (int j = 0; j < 8; j++)
            #pragma unroll
            for (int i = 0; i < 4; i++) o[mi][j][i] = 0.f;

    auto issue_tile = [&](int t, int b) {
        const int k0 = t * 64;
        const uint32_t xb = smb + (uint32_t)(b * PBUF_H) * 2u;
        const uint32_t wb = smb + (uint32_t)((2 + b) * PBUF_H) * 2u;
        #pragma unroll
        for (int l = 0; l < 4; l++) {
            int idx = tid + l * 256;
            int r = idx >> 3, c = idx & 7;
            CP_ASYNC16(xb + (uint32_t)(r * PH_STRIDE + c * 8) * 2u,
                       &g_xh[(size_t)(rowBase + r) * DM + k0 + c * 8]);
            CP_ASYNC16(wb + (uint32_t)(r * PH_STRIDE + c * 8) * 2u,
                       &Wh[(size_t)r * DM + k0 + c * 8]);
        }
        CP_COMMIT();
    };

    issue_tile(0, 0);

    const int arow0 = wr * 32 + gid;
    const int arow1 = wr * 32 + 16 + gid;

    for (int t = 0; t < 32; t++) {
        if (t < 31) { issue_tile(t + 1, (t + 1) & 1); CP_WAIT1(); }
        else        { CP_WAIT0(); }
        __syncthreads();

        const __half* xb = xs + (t & 1) * PBUF_H;
        const __half* wb = ws + (t & 1) * PBUF_H;

        #pragma unroll
        for (int ks = 0; ks < 4; ks++) {
            const int k = ks * 16 + 2 * qid;
            uint32_t a[2][4];
            a[0][0] = *(const uint32_t*)&xb[arow0       * PH_STRIDE + k];
            a[0][1] = *(const uint32_t*)&xb[(arow0 + 8) * PH_STRIDE + k];
            a[0][2] = *(const uint32_t*)&xb[arow0       * PH_STRIDE + k + 8];
            a[0][3] = *(const uint32_t*)&xb[(arow0 + 8) * PH_STRIDE + k + 8];
            a[1][0] = *(const uint32_t*)&xb[arow1       * PH_STRIDE + k];
            a[1][1] = *(const uint32_t*)&xb[(arow1 + 8) * PH_STRIDE + k];
            a[1][2] = *(const uint32_t*)&xb[arow1       * PH_STRIDE + k + 8];
            a[1][3] = *(const uint32_t*)&xb[(arow1 + 8) * PH_STRIDE + k + 8];
            #pragma unroll
            for (int j = 0; j < 8; j++) {
                int n = wc * 64 + 8 * j + gid;
                uint32_t b0 = *(const uint32_t*)&wb[n * PH_STRIDE + k];
                uint32_t b1 = *(const uint32_t*)&wb[n * PH_STRIDE + k + 8];
                mma16(o[0][j][0], o[0][j][1], o[0][j][2], o[0][j][3],
                      a[0][0], a[0][1], a[0][2], a[0][3], b0, b1);
                mma16(o[1][j][0], o[1][j][1], o[1][j][2], o[1][j][3],
                      a[1][0], a[1][1], a[1][2], a[1][3], b0, b1);
            }
        }
        __syncthreads();
    }

    // ---------------- epilogue ----------------
    if (blockIdx.z == 0) {
        #pragma unroll
        for (int mi = 0; mi < 2; mi++) {
            int row = rowBase + wr * 32 + mi * 16 + gid;
            #pragma unroll
            for (int j = 0; j < 8; j++) {
                int col = wc * 64 + 8 * j + 2 * qid;
                float2 bb = *(const float2*)&bias[col];
                *(float2*)&g_Q[(size_t)row * DK + col] =
                    make_float2(o[mi][j][0] + bb.x, o[mi][j][1] + bb.y);
                *(float2*)&g_Q[(size_t)(row + 8) * DK + col] =
                    make_float2(o[mi][j][2] + bb.x, o[mi][j][3] + bb.y);
            }
        }
    } else if (blockIdx.z == 1) {
        #pragma unroll
        for (int mi = 0; mi < 2; mi++) {
            int row = rowBase + wr * 32 + mi * 16 + gid;
            #pragma unroll
            for (int j = 0; j < 8; j++) {
                int col = wc * 64 + 8 * j + 2 * qid;
                float2 bb = *(const float2*)&bias[col];
                *(uint32_t*)&g_Kh[(size_t)row * DK + col] =
                    h2(o[mi][j][0] + bb.x, o[mi][j][1] + bb.y);
                *(uint32_t*)&g_Kh[(size_t)(row + 8) * DK + col] =
                    h2(o[mi][j][2] + bb.x, o[mi][j][3] + bb.y);
            }
        }
    } else {
        __half* stg = psm;   // [128][136] halves = 34816 B (fits)
        __syncthreads();
        #pragma unroll
        for (int mi = 0; mi < 2; mi++) {
            int row = wr * 32 + mi * 16 + gid;
            #pragma unroll
            for (int j = 0; j < 8; j++) {
                int col = wc * 64 + 8 * j + 2 * qid;
                float2 bb = *(const float2*)&bias[col];
                *(uint32_t*)&stg[row * PSTG_STRIDE + col] =
                    h2(o[mi][j][0] + bb.x, o[mi][j][1] + bb.y);
                *(uint32_t*)&stg[(row + 8) * PSTG_STRIDE + col] =
                    h2(o[mi][j][2] + bb.x, o[mi][j][3] + bb.y);
            }
        }
        __syncthreads();
        for (int idx = tid; idx < 128 * 64; idx += 256) {
            int d = idx >> 6, rp = idx & 63;
            __half lo = stg[(2 * rp)     * PSTG_STRIDE + d];
            __half hi = stg[(2 * rp + 1) * PSTG_STRIDE + d];
            __half2 p = __halves2half2(lo, hi);
            *(uint32_t*)&g_Vth[(size_t)d * SEQ + rowBase + 2 * rp] =
                *reinterpret_cast<uint32_t*>(&p);
        }
    }
}

// ============================================================================
// Kernel 2: fp16 mma.sync flash attention, split-KV x2, cp.async double-buffer.
//   NEW: P never leaves registers — the S output fragment IS the PV A-operand
//   fragment (a0..a3 for k-chunk ks = h2 of s[2ks], s[2ks+1]).  P smem region,
//   its STS/LDS, and both __syncwarp's removed.  Bit-identical numerics.
// ============================================================================
#define KS_STRIDE 136
#define VT_STRIDE 72
#define KV_BUF_H  (64 * KS_STRIDE + 128 * VT_STRIDE)   // 17920 halves / buffer
#define VT_OFF_H  (64 * KS_STRIDE)                     // 8704
#define ATTN_SMEM_B (2 * KV_BUF_H * 2)                 // 71680 bytes

__global__ __launch_bounds__(256)
void attn_kernel()
{
    extern __shared__ __half smh[];
    const uint32_t smb = smem_u32(smh);
    const int tid  = threadIdx.x;
    const int wid  = tid >> 5;
    const int lane = tid & 31;
    const int gid  = lane >> 2;
    const int qid  = lane & 3;
    const int qbase = blockIdx.x * 128;
    const int split = blockIdx.y;
    const int r0 = (wid << 4) + gid;
    const int kvbase = split * 4096;

    const float qscale = 1.4426950408889634f * 0.08838834764831845f;
    uint32_t qf[8][4];
    {
        const float* q0 = &g_Q[(size_t)(qbase + r0) * DK];
        const float* q1 = &g_Q[(size_t)(qbase + r0 + 8) * DK];
        #pragma unroll
        for (int ks = 0; ks < 8; ks++) {
            const int k = ks * 16 + 2 * qid;
            qf[ks][0] = h2(q0[k]     * qscale, q0[k + 1] * qscale);
            qf[ks][1] = h2(q1[k]     * qscale, q1[k + 1] * qscale);
            qf[ks][2] = h2(q0[k + 8] * qscale, q0[k + 9] * qscale);
            qf[ks][3] = h2(q1[k + 8] * qscale, q1[k + 9] * qscale);
        }
    }

    float o[16][4];
    #pragma unroll
    for (int j = 0; j < 16; j++)
        #pragma unroll
        for (int i = 0; i < 4; i++) o[j][i] = 0.f;
    float lsum0 = 0.f, lsum1 = 0.f;

    auto issue_tile = [&](int t, int b) {
        const int kv0 = kvbase + t * 64;
        const uint32_t bb = smb + (uint32_t)(b * KV_BUF_H) * 2u;
        #pragma unroll
        for (int l = 0; l < 8; l++) {
            int idx = tid + l * 256;
            if (idx < 1024) {
                int r = idx >> 4, c = idx & 15;
                CP_ASYNC16(bb + (uint32_t)(r * KS_STRIDE * 2 + c * 16),
                           &g_Kh[(size_t)(kv0 + r) * DK + c * 8]);
            } else {
                int v = idx - 1024;
                int d = v >> 3, c = v & 7;
                CP_ASYNC16(bb + (uint32_t)(VT_OFF_H * 2 + d * VT_STRIDE * 2 + c * 16),
                           &g_Vth[(size_t)d * SEQ + kv0 + c * 8]);
            }
        }
        CP_COMMIT();
    };

    issue_tile(0, 0);

    for (int t = 0; t < 64; t++) {
        if (t < 63) { issue_tile(t + 1, (t + 1) & 1); CP_WAIT1(); }
        else        { CP_WAIT0(); }
        __syncthreads();

        const __half* kb = smh + (t & 1) * KV_BUF_H;
        const __half* vb = kb + VT_OFF_H;

        // ---- S = Q K^T ----
        float s[8][4];
        #pragma unroll
        for (int j = 0; j < 8; j++)
            #pragma unroll
            for (int i = 0; i < 4; i++) s[j][i] = 0.f;

        #pragma unroll
        for (int ks = 0; ks < 8; ks++) {
            const int k = ks * 16 + 2 * qid;
            #pragma unroll
            for (int j = 0; j < 8; j++) {
                const int n = 8 * j + gid;
                uint32_t b0 = *(const uint32_t*)&kb[n * KS_STRIDE + k];
                uint32_t b1 = *(const uint32_t*)&kb[n * KS_STRIDE + k + 8];
                mma16(s[j][0], s[j][1], s[j][2], s[j][3],
                      qf[ks][0], qf[ks][1], qf[ks][2], qf[ks][3], b0, b1);
            }
        }

        // ---- softmax (exp2; Q pre-scaled), quad rowsums ----
        float ps0 = 0.f, ps1 = 0.f;
        #pragma unroll
        for (int j = 0; j < 8; j++) {
            s[j][0] = ex2f(s[j][0]); s[j][1] = ex2f(s[j][1]);
            s[j][2] = ex2f(s[j][2]); s[j][3] = ex2f(s[j][3]);
            ps0 += s[j][0] + s[j][1];
            ps1 += s[j][2] + s[j][3];
        }
        ps0 += __shfl_xor_sync(0xffffffffu, ps0, 1);
        ps0 += __shfl_xor_sync(0xffffffffu, ps0, 2);
        ps1 += __shfl_xor_sync(0xffffffffu, ps1, 1);
        ps1 += __shfl_xor_sync(0xffffffffu, ps1, 2);
        lsum0 += ps0; lsum1 += ps1;

        // ---- O += P V, P entirely in registers:
        //   S output frag (rows r0/r0+8, cols 8j+2q) == PV A frag for ks:
        //   a0/a1 <- s[2ks], a2/a3 <- s[2ks+1]  (same h2 RN conversions as before)
        #pragma unroll
        for (int ks = 0; ks < 4; ks++) {
            const int k = ks * 16 + 2 * qid;
            uint32_t a0 = h2(s[2 * ks][0],     s[2 * ks][1]);
            uint32_t a1 = h2(s[2 * ks][2],     s[2 * ks][3]);
            uint32_t a2 = h2(s[2 * ks + 1][0], s[2 * ks + 1][1]);
            uint32_t a3 = h2(s[2 * ks + 1][2], s[2 * ks + 1][3]);
            #pragma unroll
            for (int j = 0; j < 16; j++) {
                const int d = 8 * j + gid;
                uint32_t b0 = *(const uint32_t*)&vb[d * VT_STRIDE + k];
                uint32_t b1 = *(const uint32_t*)&vb[d * VT_STRIDE + k + 8];
                mma16(o[j][0], o[j][1], o[j][2], o[j][3], a0, a1, a2, a3, b0, b1);
            }
        }
        __syncthreads();   // KV buffer free for re-issue
    }

    float* Op = g_Opart + (size_t)split * SEQ * DK;
    #pragma unroll
    for (int j = 0; j < 16; j++) {
        int col = 8 * j + 2 * qid;
        *(float2*)&Op[(size_t)(qbase + r0) * DK + col]     = make_float2(o[j][0], o[j][1]);
        *(float2*)&Op[(size_t)(qbase + r0 + 8) * DK + col] = make_float2(o[j][2], o[j][3]);
    }
    if (qid == 0) {
        g_lpart[split * SEQ + qbase + r0]     = lsum0;
        g_lpart[split * SEQ + qbase + r0 + 8] = lsum1;
    }
}

// ============================================================================
// Kernel 3: combine splits.  out = (O0 + O1) / (l0 + l1)
// ============================================================================
__global__ __launch_bounds__(256)
void combine_kernel(float* __restrict__ out)
{
    int idx = blockIdx.x * 256 + threadIdx.x;
    int r = idx >> 5, c4 = (idx & 31) * 4;
    float inv = 1.f / (g_lpart[r] + g_lpart[SEQ + r]);
    float4 a = *(const float4*)&g_Opart[(size_t)r * DK + c4];
    float4 b = *(const float4*)&g_Opart[(size_t)(SEQ + r) * DK + c4];
    float4 o;
    o.x = (a.x + b.x) * inv; o.y = (a.y + b.y) * inv;
    o.z = (a.z + b.z) * inv; o.w = (a.w + b.w) * inv;
    *(float4*)&out[(size_t)r * DK + c4] = o;
}

// ---------------------------------------------------------------------------
extern "C" void kernel_launch(void* const* d_in, const int* in_sizes, int n_in,
                              void* d_out, int out_size)
{
    (void)in_sizes; (void)n_in; (void)out_size;
    const float* x  = (const float*)d_in[0];
    const float* Wq = (const float*)d_in[1];
    const float* bq = (const float*)d_in[2];
    const float* Wk = (const float*)d_in[3];
    const float* bk = (const float*)d_in[4];
    const float* Wv = (const float*)d_in[5];
    const float* bv = (const float*)d_in[6];
    float* out = (float*)d_out;

    cudaFuncSetAttribute(proj_tc_kernel,
                         cudaFuncAttributeMaxDynamicSharedMemorySize, PROJ_SMEM_B);
    cudaFuncSetAttribute(attn_kernel,
                         cudaFuncAttributeMaxDynamicSharedMemorySize, ATTN_SMEM_B);

    // fp32 -> fp16 conversion (x and weights)
    __half *d_xh, *d_wqh, *d_wkh, *d_wvh;
    cudaGetSymbolAddress((void**)&d_xh,  g_xh);
    cudaGetSymbolAddress((void**)&d_wqh, g_Wqh);
    cudaGetSymbolAddress((void**)&d_wkh, g_Wkh);
    cudaGetSymbolAddress((void**)&d_wvh, g_Wvh);
    const int n4x = SEQ * DM / 4;
    const int n4w = DK * DM / 4;
    cvt_kernel<<<(n4x + 255) / 256, 256>>>(x,  d_xh,  n4x);
    cvt_kernel<<<(n4w + 255) / 256, 256>>>(Wq, d_wqh, n4w);
    cvt_kernel<<<(n4w + 255) / 256, 256>>>(Wk, d_wkh, n4w);
    cvt_kernel<<<(n4w + 255) / 256, 256>>>(Wv, d_wvh, n4w);

    dim3 gProj(SEQ / 128, 1, 3);
    proj_tc_kernel<<<gProj, 256, PROJ_SMEM_B>>>(bq, bk, bv);

    dim3 gAttn(SEQ / 128, 2);
    attn_kernel<<<gAttn, 256, ATTN_SMEM_B>>>();

    combine_kernel<<<SEQ * DK / 4 / 256, 256>>>(out);
}